// round 1
// baseline (speedup 1.0000x reference)
#include <cuda_runtime.h>
#include <math.h>

#define EPSY (1.0f/137.0f)
#define NEGINF (-3.402823466e38f)

// ---------------- scratch (static device memory; no allocations) -------------
__device__ float g_qkv[4096 * 2304];   // stage-1 output (q|k|v per token)
__device__ float g_att[4096 * 768];    // attention output, [B*T, C]
__device__ float g_xn[4096];           // row norms of x
__device__ float g_an[4096];           // row norms of attention output
__device__ float g_wn1[2304];          // col norms of W_attn
__device__ float g_wn2[768];           // col norms of W_proj

// ---------------- row sum-of-squares: one warp per row ----------------------
__global__ void rownorm_k(const float* __restrict__ X, float* __restrict__ o,
                          int M, int K) {
    int row  = blockIdx.x * 8 + (threadIdx.x >> 5);
    int lane = threadIdx.x & 31;
    if (row >= M) return;
    const float* p = X + (long)row * K;
    float s = 0.f;
    for (int k = lane; k < K; k += 32) { float v = p[k]; s = fmaf(v, v, s); }
    #pragma unroll
    for (int off = 16; off; off >>= 1) s += __shfl_xor_sync(0xffffffffu, s, off);
    if (!lane) o[row] = s;
}

// ---------------- column sum-of-squares: one thread per column --------------
__global__ void colnorm_k(const float* __restrict__ W, float* __restrict__ o,
                          int K, int N) {
    int n = blockIdx.x * blockDim.x + threadIdx.x;
    if (n >= N) return;
    float s = 0.f;
    for (int k = 0; k < K; k++) { float v = W[(long)k * N + n]; s = fmaf(v, v, s); }
    o[n] = s;
}

// ---------------- fused SGEMM + Yat epilogue --------------------------------
// C[row,col] = ( dot^2 / (rn[row] + cn[col] - 2*dot + EPS) + bias[col] ) * scaleF
// scaleF = (sqrt(F)/log1p(F))^alpha
#define GBM 128
#define GBN 128
#define GBK 16

__global__ __launch_bounds__(256)
void gemm_yat_k(const float* __restrict__ A, const float* __restrict__ B,
                const float* __restrict__ bias, const float* __restrict__ rn,
                const float* __restrict__ cn, const float* __restrict__ alphaPtr,
                float* __restrict__ Cout, int M, int N, int K, float baseF) {
    __shared__ float As[GBK][GBM];
    __shared__ float Bs[GBK][GBN];

    int tid = threadIdx.x;
    int tx = tid & 15, ty = tid >> 4;
    int M0 = blockIdx.y * GBM, N0 = blockIdx.x * GBN;

    float acc[8][8];
    #pragma unroll
    for (int i = 0; i < 8; i++)
        #pragma unroll
        for (int j = 0; j < 8; j++) acc[i][j] = 0.f;

    for (int k0 = 0; k0 < K; k0 += GBK) {
        // A tile: 128 rows x 16 k -> store transposed As[k][m]
        #pragma unroll
        for (int l = 0; l < 2; l++) {
            int f = tid * 2 + l;                 // 0..511 float4s
            int row = f >> 2, k4 = (f & 3) * 4;
            float4 v = *(const float4*)&A[(long)(M0 + row) * K + k0 + k4];
            As[k4 + 0][row] = v.x; As[k4 + 1][row] = v.y;
            As[k4 + 2][row] = v.z; As[k4 + 3][row] = v.w;
        }
        // B tile: 16 rows x 128 cols -> natural Bs[k][n]
        #pragma unroll
        for (int l = 0; l < 2; l++) {
            int f = tid * 2 + l;
            int row = f >> 5, c4 = (f & 31) * 4;
            *(float4*)&Bs[row][c4] = *(const float4*)&B[(long)(k0 + row) * N + N0 + c4];
        }
        __syncthreads();

        #pragma unroll
        for (int kk = 0; kk < GBK; kk++) {
            float a[8], b[8];
            *(float4*)&a[0] = *(float4*)&As[kk][ty * 8];
            *(float4*)&a[4] = *(float4*)&As[kk][ty * 8 + 4];
            *(float4*)&b[0] = *(float4*)&Bs[kk][tx * 8];
            *(float4*)&b[4] = *(float4*)&Bs[kk][tx * 8 + 4];
            #pragma unroll
            for (int i = 0; i < 8; i++)
                #pragma unroll
                for (int j = 0; j < 8; j++)
                    acc[i][j] = fmaf(a[i], b[j], acc[i][j]);
        }
        __syncthreads();
    }

    float alpha  = __ldg(alphaPtr);
    float scaleF = powf(sqrtf(baseF) / logf(1.0f + baseF), alpha);

    #pragma unroll
    for (int i = 0; i < 8; i++) {
        int row = M0 + ty * 8 + i;
        float xn = rn[row];
        #pragma unroll
        for (int j = 0; j < 8; j += 4) {
            float4 r;
            float* pr = (float*)&r;
            #pragma unroll
            for (int u = 0; u < 4; u++) {
                int col   = N0 + tx * 8 + j + u;
                float dot = acc[i][j + u];
                float den = xn + cn[col] - 2.0f * dot + EPSY;
                pr[u] = (dot * dot / den + bias[col]) * scaleF;
            }
            *(float4*)&Cout[(long)row * N + N0 + tx * 8 + j] = r;
        }
    }
}

// ---------------- Yat flash attention ---------------------------------------
// score = (s/8)^2 / (qn + kn - 2*(s/8) + EPS), causal mask, online softmax, P@V
#define AQ 64
#define AK 64
#define AD 64
#define PSTR 68
#define ATTN_SMEM_FLOATS (AD*AQ + AD*AK + AK*AD + AK*PSTR + AQ + AK)

__global__ __launch_bounds__(256)
void attn_k(const float* __restrict__ qkv, float* __restrict__ outp) {
    extern __shared__ float sm[];
    float* Qs = sm;                       // [AD][AQ] transposed
    float* Ks = Qs + AD * AQ;             // [AD][AK] transposed
    float* Vs = Ks + AD * AK;             // [AK][AD] natural
    float* Ps = Vs + AK * AD;             // [AQ rows][PSTR] (row-major, padded)
    float* qn = Ps + AK * PSTR;           // [AQ]
    float* kn = qn + AQ;                  // [AK]

    int tid = threadIdx.x;
    int tx = tid & 15, ty = tid >> 4;
    int qt = blockIdx.x, h = blockIdx.y, b = blockIdx.z;
    int q0 = qt * AQ;
    const int T = 1024, C3 = 2304;
    long base = (long)b * T * C3;
    int qcol = h * 64, kcol = 768 + h * 64, vcol = 1536 + h * 64;

    // Q tile (transposed store) : 1024 float4 / 256 threads
    #pragma unroll
    for (int l = 0; l < 4; l++) {
        int f = tid * 4 + l;
        int qr = f >> 4, d4 = (f & 15) * 4;
        float4 v = *(const float4*)&qkv[base + (long)(q0 + qr) * C3 + qcol + d4];
        Qs[(d4 + 0) * AQ + qr] = v.x; Qs[(d4 + 1) * AQ + qr] = v.y;
        Qs[(d4 + 2) * AQ + qr] = v.z; Qs[(d4 + 3) * AQ + qr] = v.w;
    }
    __syncthreads();
    if (tid < AQ) {
        float s = 0.f;
        for (int d = 0; d < AD; d++) { float v = Qs[d * AQ + tid]; s = fmaf(v, v, s); }
        qn[tid] = s;
    }
    __syncthreads();

    float m[4], lsum[4], O[4][4];
    #pragma unroll
    for (int i = 0; i < 4; i++) {
        m[i] = NEGINF; lsum[i] = 0.f;
        #pragma unroll
        for (int j = 0; j < 4; j++) O[i][j] = 0.f;
    }

    int ktiles = qt + 1;
    for (int kt = 0; kt < ktiles; kt++) {
        int k0 = kt * AK;
        // load K (transposed) and V (natural)
        #pragma unroll
        for (int l = 0; l < 4; l++) {
            int f = tid * 4 + l;
            int kr = f >> 4, d4 = (f & 15) * 4;
            float4 kv = *(const float4*)&qkv[base + (long)(k0 + kr) * C3 + kcol + d4];
            Ks[(d4 + 0) * AK + kr] = kv.x; Ks[(d4 + 1) * AK + kr] = kv.y;
            Ks[(d4 + 2) * AK + kr] = kv.z; Ks[(d4 + 3) * AK + kr] = kv.w;
            float4 vv = *(const float4*)&qkv[base + (long)(k0 + kr) * C3 + vcol + d4];
            *(float4*)&Vs[kr * AD + d4] = vv;
        }
        __syncthreads();
        if (tid < AK) {
            float s = 0.f;
            for (int d = 0; d < AD; d++) { float v = Ks[d * AK + tid]; s = fmaf(v, v, s); }
            kn[tid] = s;
        }
        __syncthreads();

        // S = Q K^T  (each thread: 4x4)
        float S[4][4];
        #pragma unroll
        for (int i = 0; i < 4; i++)
            #pragma unroll
            for (int j = 0; j < 4; j++) S[i][j] = 0.f;
        for (int d = 0; d < AD; d++) {
            float4 qv = *(const float4*)&Qs[d * AQ + ty * 4];
            float4 kv = *(const float4*)&Ks[d * AK + tx * 4];
            float qa[4] = {qv.x, qv.y, qv.z, qv.w};
            float ka[4] = {kv.x, kv.y, kv.z, kv.w};
            #pragma unroll
            for (int i = 0; i < 4; i++)
                #pragma unroll
                for (int j = 0; j < 4; j++)
                    S[i][j] = fmaf(qa[i], ka[j], S[i][j]);
        }

        // Yat score transform + causal mask
        float knj[4];
        #pragma unroll
        for (int j = 0; j < 4; j++) knj[j] = kn[tx * 4 + j];
        bool diag = (kt == qt);
        #pragma unroll
        for (int i = 0; i < 4; i++) {
            float qni = qn[ty * 4 + i];
            #pragma unroll
            for (int j = 0; j < 4; j++) {
                float sc = S[i][j] * 0.125f;
                float den = qni + knj[j] - 2.0f * sc + EPSY;
                float lg = sc * sc / den;
                if (diag && (tx * 4 + j) > (ty * 4 + i)) lg = NEGINF;
                S[i][j] = lg;
            }
        }

        // online softmax (rows reduced across the 16-lane tx group)
        #pragma unroll
        for (int i = 0; i < 4; i++) {
            float mx = fmaxf(fmaxf(S[i][0], S[i][1]), fmaxf(S[i][2], S[i][3]));
            #pragma unroll
            for (int off = 8; off; off >>= 1)
                mx = fmaxf(mx, __shfl_xor_sync(0xffffffffu, mx, off, 16));
            float mn = fmaxf(m[i], mx);
            float corr = __expf(m[i] - mn);
            float rs = 0.f;
            #pragma unroll
            for (int j = 0; j < 4; j++) {
                float p = __expf(S[i][j] - mn);
                S[i][j] = p; rs += p;
            }
            #pragma unroll
            for (int off = 8; off; off >>= 1)
                rs += __shfl_xor_sync(0xffffffffu, rs, off, 16);
            lsum[i] = lsum[i] * corr + rs;
            m[i] = mn;
            #pragma unroll
            for (int j = 0; j < 4; j++) O[i][j] *= corr;
        }

        // stage P through smem (row-major, padded stride)
        #pragma unroll
        for (int i = 0; i < 4; i++)
            *(float4*)&Ps[(ty * 4 + i) * PSTR + tx * 4] = *(float4*)&S[i][0];
        __syncthreads();

        // O += P @ V
        for (int j = 0; j < AK; j++) {
            float4 vv = *(const float4*)&Vs[j * AD + tx * 4];
            float va[4] = {vv.x, vv.y, vv.z, vv.w};
            float p0 = Ps[(ty * 4 + 0) * PSTR + j];
            float p1 = Ps[(ty * 4 + 1) * PSTR + j];
            float p2 = Ps[(ty * 4 + 2) * PSTR + j];
            float p3 = Ps[(ty * 4 + 3) * PSTR + j];
            #pragma unroll
            for (int c = 0; c < 4; c++) {
                O[0][c] = fmaf(p0, va[c], O[0][c]);
                O[1][c] = fmaf(p1, va[c], O[1][c]);
                O[2][c] = fmaf(p2, va[c], O[2][c]);
                O[3][c] = fmaf(p3, va[c], O[3][c]);
            }
        }
        __syncthreads();
    }

    // normalize and write [B*T, C] with col = h*64 + d
    #pragma unroll
    for (int i = 0; i < 4; i++) {
        float inv = 1.0f / lsum[i];
        int row = b * T + q0 + ty * 4 + i;
        float4 st = make_float4(O[i][0] * inv, O[i][1] * inv,
                                O[i][2] * inv, O[i][3] * inv);
        *(float4*)&outp[(long)row * 768 + h * 64 + tx * 4] = st;
    }
}

// ---------------- launch ----------------------------------------------------
extern "C" void kernel_launch(void* const* d_in, const int* in_sizes, int n_in,
                              void* d_out, int out_size) {
    const float* x          = (const float*)d_in[0];
    // d_in[1] = mask (tril causal) — applied analytically
    const float* W_attn     = (const float*)d_in[2];
    const float* b_attn     = (const float*)d_in[3];
    const float* alpha_attn = (const float*)d_in[4];
    const float* W_proj     = (const float*)d_in[5];
    const float* b_proj     = (const float*)d_in[6];
    const float* alpha_proj = (const float*)d_in[7];
    float* out = (float*)d_out;

    float *p_qkv, *p_att, *p_xn, *p_an, *p_wn1, *p_wn2;
    cudaGetSymbolAddress((void**)&p_qkv, g_qkv);
    cudaGetSymbolAddress((void**)&p_att, g_att);
    cudaGetSymbolAddress((void**)&p_xn,  g_xn);
    cudaGetSymbolAddress((void**)&p_an,  g_an);
    cudaGetSymbolAddress((void**)&p_wn1, g_wn1);
    cudaGetSymbolAddress((void**)&p_wn2, g_wn2);

    const int M = 4096, C = 768, F1 = 2304;

    // stage 1: norms + fused GEMM-Yat -> qkv
    rownorm_k<<<M / 8, 256>>>(x, p_xn, M, C);
    colnorm_k<<<F1 / 256, 256>>>(W_attn, p_wn1, C, F1);
    gemm_yat_k<<<dim3(F1 / GBN, M / GBM), 256>>>(
        x, W_attn, b_attn, p_xn, p_wn1, alpha_attn, p_qkv, M, F1, C, (float)F1);

    // stage 2: Yat attention
    static int smem_set = 0;
    (void)smem_set;
    cudaFuncSetAttribute(attn_k, cudaFuncAttributeMaxDynamicSharedMemorySize,
                         ATTN_SMEM_FLOATS * (int)sizeof(float));
    attn_k<<<dim3(16, 12, 4), 256, ATTN_SMEM_FLOATS * sizeof(float)>>>(p_qkv, p_att);

    // stage 3: norms + fused GEMM-Yat -> out
    rownorm_k<<<M / 8, 256>>>(p_att, p_an, M, C);
    colnorm_k<<<C / 256, 256>>>(W_proj, p_wn2, C, C);
    gemm_yat_k<<<dim3(C / GBN, M / GBM), 256>>>(
        p_att, W_proj, b_proj, p_an, p_wn2, alpha_proj, out, M, C, C, (float)C);
}

// round 5
// speedup vs baseline: 1.5106x; 1.5106x over previous
#include <cuda_runtime.h>
#include <cuda_bf16.h>
#include <cstdint>
#include <math.h>

#define EPSY (1.0f/137.0f)
#define NEGINF (-3.402823466e38f)

// ================= helpers ===================================================
__device__ __forceinline__ uint32_t smem_u32(const void* p) {
    uint32_t a;
    asm("{ .reg .u64 t; cvta.to.shared.u64 t, %1; cvt.u32.u64 %0, t; }"
        : "=r"(a) : "l"(p));
    return a;
}
__device__ __forceinline__ void cp16(uint32_t s, const void* g) {
    asm volatile("cp.async.cg.shared.global [%0], [%1], 16;" :: "r"(s), "l"(g));
}
#define CP_COMMIT() asm volatile("cp.async.commit_group;" ::: "memory")
#define CP_WAIT1()  asm volatile("cp.async.wait_group 1;" ::: "memory")
#define CP_WAIT0()  asm volatile("cp.async.wait_group 0;" ::: "memory")

__device__ __forceinline__ void ldsm4(uint32_t* r, uint32_t addr) {
    asm volatile("ldmatrix.sync.aligned.m8n8.x4.shared.b16 {%0,%1,%2,%3}, [%4];"
        : "=r"(r[0]), "=r"(r[1]), "=r"(r[2]), "=r"(r[3]) : "r"(addr));
}
__device__ __forceinline__ void mma16816(float* d, const uint32_t* a, const uint32_t* b) {
    asm volatile(
        "mma.sync.aligned.m16n8k16.row.col.f32.bf16.bf16.f32 "
        "{%0,%1,%2,%3}, {%4,%5,%6,%7}, {%8,%9}, {%0,%1,%2,%3};"
        : "+f"(d[0]), "+f"(d[1]), "+f"(d[2]), "+f"(d[3])
        : "r"(a[0]), "r"(a[1]), "r"(a[2]), "r"(a[3]), "r"(b[0]), "r"(b[1]));
}

// ================= scratch (static device memory) ===========================
__device__ float g_qkv[4096 * 2304];
__device__ float g_att[4096 * 768];
__device__ float g_xn[4096];
__device__ float g_an[4096];
__device__ float g_wn1[2304];
__device__ float g_wn2[768];
__device__ __nv_bfloat16 g_xhi[4096 * 768], g_xlo[4096 * 768];
__device__ __nv_bfloat16 g_ahi[4096 * 768], g_alo[4096 * 768];
__device__ __nv_bfloat16 g_w1hi[2304 * 768], g_w1lo[2304 * 768];
__device__ __nv_bfloat16 g_w2hi[768 * 768], g_w2lo[768 * 768];

// ================= prep kernels =============================================
__global__ void split_norm_k(const float* __restrict__ X, __nv_bfloat16* __restrict__ H,
                             __nv_bfloat16* __restrict__ L, float* __restrict__ nrm,
                             int M, int K) {
    int row = blockIdx.x * 8 + (threadIdx.x >> 5);
    int lane = threadIdx.x & 31;
    if (row >= M) return;
    const float* p = X + (long)row * K;
    float s = 0.f;
    for (int k = lane; k < K; k += 32) {
        float v = p[k];
        s = fmaf(v, v, s);
        __nv_bfloat16 hb = __float2bfloat16(v);
        H[(long)row * K + k] = hb;
        L[(long)row * K + k] = __float2bfloat16(v - __bfloat162float(hb));
    }
    #pragma unroll
    for (int o = 16; o; o >>= 1) s += __shfl_xor_sync(0xffffffffu, s, o);
    if (!lane) nrm[row] = s;
}

__global__ void rownorm_k(const float* __restrict__ X, float* __restrict__ o, int M, int K) {
    int row = blockIdx.x * 8 + (threadIdx.x >> 5);
    int lane = threadIdx.x & 31;
    if (row >= M) return;
    const float* p = X + (long)row * K;
    float s = 0.f;
    for (int k = lane; k < K; k += 32) { float v = p[k]; s = fmaf(v, v, s); }
    #pragma unroll
    for (int o2 = 16; o2; o2 >>= 1) s += __shfl_xor_sync(0xffffffffu, s, o2);
    if (!lane) o[row] = s;
}

__global__ void colnorm_k(const float* __restrict__ W, float* __restrict__ o, int K, int N) {
    int n = blockIdx.x * blockDim.x + threadIdx.x;
    if (n >= N) return;
    float s = 0.f;
    for (int k = 0; k < K; k++) { float v = W[(long)k * N + n]; s = fmaf(v, v, s); }
    o[n] = s;
}

// W [K,N] fp32 -> transposed bf16 hi/lo [N,K]
__global__ void wtrans_split_k(const float* __restrict__ W, __nv_bfloat16* __restrict__ Th,
                               __nv_bfloat16* __restrict__ Tl, int K, int N) {
    __shared__ float t[32][33];
    int n0 = blockIdx.x * 32, k0 = blockIdx.y * 32;
    int tx = threadIdx.x, ty = threadIdx.y;  // (32, 8)
    #pragma unroll
    for (int j = 0; j < 32; j += 8)
        t[ty + j][tx] = W[(long)(k0 + ty + j) * N + n0 + tx];
    __syncthreads();
    #pragma unroll
    for (int j = 0; j < 32; j += 8) {
        float v = t[tx][ty + j];
        __nv_bfloat16 hb = __float2bfloat16(v);
        Th[(long)(n0 + ty + j) * K + k0 + tx] = hb;
        Tl[(long)(n0 + ty + j) * K + k0 + tx] = __float2bfloat16(v - __bfloat162float(hb));
    }
}

// ================= HMMA Yat-GEMM =============================================
// D = A @ B^T, A [M,K] bf16 hi/lo row-major, B [N,K] bf16 hi/lo row-major.
// 3-product split: hi*hi + hi*lo + lo*hi, fp32 accum.
// Epilogue: (dot^2/(rn+cn-2dot+eps) + bias) * (sqrt(F)/log1p(F))^alpha
#define BK 64
#define STR 144                   // smem row stride bytes (64 bf16 + 8 pad)
#define MAT_BYTES (128 * STR)     // 18432
#define BUF_BYTES (4 * MAT_BYTES) // 73728
#define GEMM_SMEM (2 * BUF_BYTES) // 147456

__global__ __launch_bounds__(256, 1)
void gemm_mma_k(const __nv_bfloat16* __restrict__ Ah, const __nv_bfloat16* __restrict__ Al,
                const __nv_bfloat16* __restrict__ Bh, const __nv_bfloat16* __restrict__ Bl,
                const float* __restrict__ bias, const float* __restrict__ rn,
                const float* __restrict__ cn, const float* __restrict__ alphaPtr,
                float* __restrict__ Cout, int M, int N, int K, float baseF) {
    extern __shared__ char smc[];
    uint32_t sb = smem_u32(smc);
    int tid = threadIdx.x, wid = tid >> 5, lane = tid & 31;
    int M0 = blockIdx.y * 128, N0 = blockIdx.x * 128;
    int wm = wid & 1, wn = wid >> 1;           // warp tile: 64(m) x 32(n)

    float acc[4][4][4];
    #pragma unroll
    for (int i = 0; i < 4; i++)
        #pragma unroll
        for (int j = 0; j < 4; j++)
            #pragma unroll
            for (int u = 0; u < 4; u++) acc[i][j][u] = 0.f;

    const int NCH = K / BK;  // 12

    // ---- cp.async chunk loader: 16 x 16B per thread (Ah,Al,Bh,Bl tiles) ----
    auto load_chunk = [&](int c, int buf) {
        int k0 = c * BK;
        uint32_t base = sb + buf * BUF_BYTES;
        #pragma unroll
        for (int l = 0; l < 4; l++) {
            int f = tid + l * 256;      // 0..1023
            int row = f >> 3, seg = f & 7;
            uint32_t so = row * STR + seg * 16;
            long ga = (long)(M0 + row) * K + k0 + seg * 8;
            long gb = (long)(N0 + row) * K + k0 + seg * 8;
            cp16(base + so,                 Ah + ga);
            cp16(base + MAT_BYTES + so,     Al + ga);
            cp16(base + 2 * MAT_BYTES + so, Bh + gb);
            cp16(base + 3 * MAT_BYTES + so, Bl + gb);
        }
    };

    load_chunk(0, 0); CP_COMMIT();
    load_chunk(1, 1); CP_COMMIT();

    int gq = lane >> 3, rq = lane & 7;
    // A ldmatrix lane row/col pieces
    int arow = wm * 64 + (gq & 1) * 8 + rq;
    int acol8 = (gq >> 1) * 8;
    // B ldmatrix (pair of n-frags) lane pieces
    int brow = wn * 32 + (gq >> 1) * 8 + rq;   // + j*8 added per pair
    int bcol8 = (gq & 1) * 8;

    for (int c = 0; c < NCH; c++) {
        if (c + 1 < NCH) { CP_WAIT1(); } else { CP_WAIT0(); }
        __syncthreads();
        uint32_t base = sb + (c & 1) * BUF_BYTES;
        uint32_t bAh = base, bAl = base + MAT_BYTES;
        uint32_t bBh = base + 2 * MAT_BYTES, bBl = base + 3 * MAT_BYTES;

        #pragma unroll
        for (int ks = 0; ks < BK / 16; ks++) {
            int kc = ks * 16;
            uint32_t ah[4][4], al[4][4], bh[4][2], bl[4][2];
            #pragma unroll
            for (int i = 0; i < 4; i++) {
                uint32_t off = (uint32_t)((arow + i * 16) * STR + (kc + acol8) * 2);
                ldsm4(ah[i], bAh + off);
                ldsm4(al[i], bAl + off);
            }
            #pragma unroll
            for (int jp = 0; jp < 2; jp++) {
                uint32_t off = (uint32_t)((brow + jp * 16) * STR + (kc + bcol8) * 2);
                uint32_t r[4];
                ldsm4(r, bBh + off);
                bh[jp * 2][0] = r[0]; bh[jp * 2][1] = r[1];
                bh[jp * 2 + 1][0] = r[2]; bh[jp * 2 + 1][1] = r[3];
                ldsm4(r, bBl + off);
                bl[jp * 2][0] = r[0]; bl[jp * 2][1] = r[1];
                bl[jp * 2 + 1][0] = r[2]; bl[jp * 2 + 1][1] = r[3];
            }
            #pragma unroll
            for (int i = 0; i < 4; i++)
                #pragma unroll
                for (int j = 0; j < 4; j++) {
                    mma16816(acc[i][j], ah[i], bh[j]);
                    mma16816(acc[i][j], ah[i], bl[j]);
                    mma16816(acc[i][j], al[i], bh[j]);
                }
        }
        if (c + 2 < NCH) {
            __syncthreads();
            load_chunk(c + 2, c & 1);
            CP_COMMIT();
        }
    }

    // ---- Yat epilogue ----
    float alpha = __ldg(alphaPtr);
    float scaleF = powf(sqrtf(baseF) / logf(1.0f + baseF), alpha);
    int tq = lane >> 2, tr = lane & 3;
    #pragma unroll
    for (int i = 0; i < 4; i++) {
        int m0 = M0 + wm * 64 + i * 16 + tq;
        float rn0 = __ldg(&rn[m0]);
        float rn1 = __ldg(&rn[m0 + 8]);
        #pragma unroll
        for (int j = 0; j < 4; j++) {
            int n0 = N0 + wn * 32 + j * 8 + tr * 2;
            float cn0 = __ldg(&cn[n0]), cn1 = __ldg(&cn[n0 + 1]);
            float bb0 = __ldg(&bias[n0]), bb1 = __ldg(&bias[n0 + 1]);
            float c0 = acc[i][j][0], c1 = acc[i][j][1];
            float c2 = acc[i][j][2], c3 = acc[i][j][3];
            float2 r0, r1;
            r0.x = (c0 * c0 / (rn0 + cn0 - 2.f * c0 + EPSY) + bb0) * scaleF;
            r0.y = (c1 * c1 / (rn0 + cn1 - 2.f * c1 + EPSY) + bb1) * scaleF;
            r1.x = (c2 * c2 / (rn1 + cn0 - 2.f * c2 + EPSY) + bb0) * scaleF;
            r1.y = (c3 * c3 / (rn1 + cn1 - 2.f * c3 + EPSY) + bb1) * scaleF;
            *(float2*)&Cout[(long)m0 * N + n0] = r0;
            *(float2*)&Cout[(long)(m0 + 8) * N + n0] = r1;
        }
    }
}

// ================= Yat flash attention ======================================
#define AQ 64
#define AK 64
#define AD 64
#define PSTR 68
#define ATTN_SMEM_FLOATS (AD * AQ + AD * AK + AK * AD + AK * PSTR + AQ + AK)

__global__ __launch_bounds__(256)
void attn_k(const float* __restrict__ qkv, float* __restrict__ outp,
            __nv_bfloat16* __restrict__ ohi, __nv_bfloat16* __restrict__ olo) {
    extern __shared__ float smf[];
    float* Qs = smf;
    float* Ks = Qs + AD * AQ;
    float* Vs = Ks + AD * AK;
    float* Ps = Vs + AK * AD;
    float* qn = Ps + AK * PSTR;
    float* kn = qn + AQ;

    int tid = threadIdx.x;
    int tx = tid & 15, ty = tid >> 4;
    int qt = blockIdx.x, h = blockIdx.y, b = blockIdx.z;
    int q0 = qt * AQ;
    const int T = 1024, C3 = 2304;
    long base = (long)b * T * C3;
    int qcol = h * 64, kcol = 768 + h * 64, vcol = 1536 + h * 64;

    #pragma unroll
    for (int l = 0; l < 4; l++) {
        int f = tid * 4 + l;
        int qr = f >> 4, d4 = (f & 15) * 4;
        float4 v = *(const float4*)&qkv[base + (long)(q0 + qr) * C3 + qcol + d4];
        Qs[(d4 + 0) * AQ + qr] = v.x; Qs[(d4 + 1) * AQ + qr] = v.y;
        Qs[(d4 + 2) * AQ + qr] = v.z; Qs[(d4 + 3) * AQ + qr] = v.w;
    }
    __syncthreads();
    if (tid < AQ) {
        float s = 0.f;
        for (int d = 0; d < AD; d++) { float v = Qs[d * AQ + tid]; s = fmaf(v, v, s); }
        qn[tid] = s;
    }
    __syncthreads();

    float m[4], lsum[4], O[4][4];
    #pragma unroll
    for (int i = 0; i < 4; i++) {
        m[i] = NEGINF; lsum[i] = 0.f;
        #pragma unroll
        for (int j = 0; j < 4; j++) O[i][j] = 0.f;
    }

    int ktiles = qt + 1;
    for (int kt = 0; kt < ktiles; kt++) {
        int k0 = kt * AK;
        #pragma unroll
        for (int l = 0; l < 4; l++) {
            int f = tid * 4 + l;
            int kr = f >> 4, d4 = (f & 15) * 4;
            float4 kv = *(const float4*)&qkv[base + (long)(k0 + kr) * C3 + kcol + d4];
            Ks[(d4 + 0) * AK + kr] = kv.x; Ks[(d4 + 1) * AK + kr] = kv.y;
            Ks[(d4 + 2) * AK + kr] = kv.z; Ks[(d4 + 3) * AK + kr] = kv.w;
            float4 vv = *(const float4*)&qkv[base + (long)(k0 + kr) * C3 + vcol + d4];
            *(float4*)&Vs[kr * AD + d4] = vv;
        }
        __syncthreads();
        if (tid < AK) {
            float s = 0.f;
            for (int d = 0; d < AD; d++) { float v = Ks[d * AK + tid]; s = fmaf(v, v, s); }
            kn[tid] = s;
        }
        __syncthreads();

        float S[4][4];
        #pragma unroll
        for (int i = 0; i < 4; i++)
            #pragma unroll
            for (int j = 0; j < 4; j++) S[i][j] = 0.f;
        for (int d = 0; d < AD; d++) {
            float4 qv = *(const float4*)&Qs[d * AQ + ty * 4];
            float4 kv = *(const float4*)&Ks[d * AK + tx * 4];
            float qa[4] = {qv.x, qv.y, qv.z, qv.w};
            float ka[4] = {kv.x, kv.y, kv.z, kv.w};
            #pragma unroll
            for (int i = 0; i < 4; i++)
                #pragma unroll
                for (int j = 0; j < 4; j++)
                    S[i][j] = fmaf(qa[i], ka[j], S[i][j]);
        }

        float knj[4];
        #pragma unroll
        for (int j = 0; j < 4; j++) knj[j] = kn[tx * 4 + j];
        bool diag = (kt == qt);
        #pragma unroll
        for (int i = 0; i < 4; i++) {
            float qni = qn[ty * 4 + i];
            #pragma unroll
            for (int j = 0; j < 4; j++) {
                float sc = S[i][j] * 0.125f;
                float den = qni + knj[j] - 2.0f * sc + EPSY;
                float lg = sc * sc / den;
                if (diag && (tx * 4 + j) > (ty * 4 + i)) lg = NEGINF;
                S[i][j] = lg;
            }
        }

        #pragma unroll
        for (int i = 0; i < 4; i++) {
            float mx = fmaxf(fmaxf(S[i][0], S[i][1]), fmaxf(S[i][2], S[i][3]));
            #pragma unroll
            for (int o = 8; o; o >>= 1)
                mx = fmaxf(mx, __shfl_xor_sync(0xffffffffu, mx, o, 16));
            float mn = fmaxf(m[i], mx);
            float corr = __expf(m[i] - mn);
            float rs = 0.f;
            #pragma unroll
            for (int j = 0; j < 4; j++) {
                float p = __expf(S[i][j] - mn);
                S[i][j] = p; rs += p;
            }
            #pragma unroll
            for (int o = 8; o; o >>= 1)
                rs += __shfl_xor_sync(0xffffffffu, rs, o, 16);
            lsum[i] = lsum[i] * corr + rs;
            m[i] = mn;
            #pragma unroll
            for (int j = 0; j < 4; j++) O[i][j] *= corr;
        }

        #pragma unroll
        for (int i = 0; i < 4; i++)
            *(float4*)&Ps[(ty * 4 + i) * PSTR + tx * 4] = *(float4*)&S[i][0];
        __syncthreads();

        for (int j = 0; j < AK; j++) {
            float4 vv = *(const float4*)&Vs[j * AD + tx * 4];
            float va[4] = {vv.x, vv.y, vv.z, vv.w};
            float p0 = Ps[(ty * 4 + 0) * PSTR + j];
            float p1 = Ps[(ty * 4 + 1) * PSTR + j];
            float p2 = Ps[(ty * 4 + 2) * PSTR + j];
            float p3 = Ps[(ty * 4 + 3) * PSTR + j];
            #pragma unroll
            for (int cc = 0; cc < 4; cc++) {
                O[0][cc] = fmaf(p0, va[cc], O[0][cc]);
                O[1][cc] = fmaf(p1, va[cc], O[1][cc]);
                O[2][cc] = fmaf(p2, va[cc], O[2][cc]);
                O[3][cc] = fmaf(p3, va[cc], O[3][cc]);
            }
        }
        __syncthreads();
    }

    #pragma unroll
    for (int i = 0; i < 4; i++) {
        float inv = 1.0f / lsum[i];
        int row = b * T + q0 + ty * 4 + i;
        long obase = (long)row * 768 + h * 64 + tx * 4;
        float v0 = O[i][0] * inv, v1 = O[i][1] * inv;
        float v2 = O[i][2] * inv, v3 = O[i][3] * inv;
        *(float4*)&outp[obase] = make_float4(v0, v1, v2, v3);
        __nv_bfloat16 h0 = __float2bfloat16(v0), h1 = __float2bfloat16(v1);
        __nv_bfloat16 h2 = __float2bfloat16(v2), h3 = __float2bfloat16(v3);
        __nv_bfloat162 hp0; hp0.x = h0; hp0.y = h1;
        __nv_bfloat162 hp1; hp1.x = h2; hp1.y = h3;
        *(__nv_bfloat162*)&ohi[obase] = hp0;
        *(__nv_bfloat162*)&ohi[obase + 2] = hp1;
        __nv_bfloat162 lp0, lp1;
        lp0.x = __float2bfloat16(v0 - __bfloat162float(h0));
        lp0.y = __float2bfloat16(v1 - __bfloat162float(h1));
        lp1.x = __float2bfloat16(v2 - __bfloat162float(h2));
        lp1.y = __float2bfloat16(v3 - __bfloat162float(h3));
        *(__nv_bfloat162*)&olo[obase] = lp0;
        *(__nv_bfloat162*)&olo[obase + 2] = lp1;
    }
}

// ================= launch ====================================================
extern "C" void kernel_launch(void* const* d_in, const int* in_sizes, int n_in,
                              void* d_out, int out_size) {
    const float* x          = (const float*)d_in[0];
    // d_in[1] = causal tril mask — applied analytically
    const float* W_attn     = (const float*)d_in[2];
    const float* b_attn     = (const float*)d_in[3];
    const float* alpha_attn = (const float*)d_in[4];
    const float* W_proj     = (const float*)d_in[5];
    const float* b_proj     = (const float*)d_in[6];
    const float* alpha_proj = (const float*)d_in[7];
    float* out = (float*)d_out;

    float *p_qkv, *p_att, *p_xn, *p_an, *p_wn1, *p_wn2;
    __nv_bfloat16 *p_xhi, *p_xlo, *p_ahi, *p_alo, *p_w1hi, *p_w1lo, *p_w2hi, *p_w2lo;
    cudaGetSymbolAddress((void**)&p_qkv, g_qkv);
    cudaGetSymbolAddress((void**)&p_att, g_att);
    cudaGetSymbolAddress((void**)&p_xn, g_xn);
    cudaGetSymbolAddress((void**)&p_an, g_an);
    cudaGetSymbolAddress((void**)&p_wn1, g_wn1);
    cudaGetSymbolAddress((void**)&p_wn2, g_wn2);
    cudaGetSymbolAddress((void**)&p_xhi, g_xhi);
    cudaGetSymbolAddress((void**)&p_xlo, g_xlo);
    cudaGetSymbolAddress((void**)&p_ahi, g_ahi);
    cudaGetSymbolAddress((void**)&p_alo, g_alo);
    cudaGetSymbolAddress((void**)&p_w1hi, g_w1hi);
    cudaGetSymbolAddress((void**)&p_w1lo, g_w1lo);
    cudaGetSymbolAddress((void**)&p_w2hi, g_w2hi);
    cudaGetSymbolAddress((void**)&p_w2lo, g_w2lo);

    const int M = 4096, C = 768, F1 = 2304;

    cudaFuncSetAttribute(gemm_mma_k, cudaFuncAttributeMaxDynamicSharedMemorySize, GEMM_SMEM);
    cudaFuncSetAttribute(attn_k, cudaFuncAttributeMaxDynamicSharedMemorySize,
                         ATTN_SMEM_FLOATS * (int)sizeof(float));

    // ---- stage 1 prep
    split_norm_k<<<M / 8, 256>>>(x, p_xhi, p_xlo, p_xn, M, C);
    wtrans_split_k<<<dim3(F1 / 32, C / 32), dim3(32, 8)>>>(W_attn, p_w1hi, p_w1lo, C, F1);
    colnorm_k<<<F1 / 256, 256>>>(W_attn, p_wn1, C, F1);

    // ---- stage 1: HMMA Yat-GEMM -> qkv
    gemm_mma_k<<<dim3(F1 / 128, M / 128), 256, GEMM_SMEM>>>(
        p_xhi, p_xlo, p_w1hi, p_w1lo, b_attn, p_xn, p_wn1, alpha_attn,
        p_qkv, M, F1, C, (float)F1);

    // ---- stage 2: Yat flash attention (+ fused bf16 split of output)
    attn_k<<<dim3(16, 12, 4), 256, ATTN_SMEM_FLOATS * sizeof(float)>>>(
        p_qkv, p_att, p_ahi, p_alo);

    // ---- stage 3 prep + HMMA Yat-GEMM -> out
    rownorm_k<<<M / 8, 256>>>(p_att, p_an, M, C);
    wtrans_split_k<<<dim3(C / 32, C / 32), dim3(32, 8)>>>(W_proj, p_w2hi, p_w2lo, C, C);
    colnorm_k<<<C / 256, 256>>>(W_proj, p_wn2, C, C);
    gemm_mma_k<<<dim3(C / 128, M / 128), 256, GEMM_SMEM>>>(
        p_ahi, p_alo, p_w2hi, p_w2lo, b_proj, p_an, p_wn2, alpha_proj,
        out, M, C, C, (float)C);
}

// round 7
// speedup vs baseline: 2.3013x; 1.5234x over previous
#include <cuda_runtime.h>
#include <cuda_bf16.h>
#include <cstdint>
#include <math.h>

#define EPSY (1.0f/137.0f)
#define NEGINF (-3.402823466e38f)

// ================= helpers ===================================================
__device__ __forceinline__ uint32_t smem_u32(const void* p) {
    uint32_t a;
    asm("{ .reg .u64 t; cvta.to.shared.u64 t, %1; cvt.u32.u64 %0, t; }"
        : "=r"(a) : "l"(p));
    return a;
}
__device__ __forceinline__ void cp16(uint32_t s, const void* g) {
    asm volatile("cp.async.cg.shared.global [%0], [%1], 16;" :: "r"(s), "l"(g));
}
#define CP_COMMIT() asm volatile("cp.async.commit_group;" ::: "memory")
#define CP_WAIT1()  asm volatile("cp.async.wait_group 1;" ::: "memory")
#define CP_WAIT0()  asm volatile("cp.async.wait_group 0;" ::: "memory")

__device__ __forceinline__ void ldsm4(uint32_t* r, uint32_t addr) {
    asm volatile("ldmatrix.sync.aligned.m8n8.x4.shared.b16 {%0,%1,%2,%3}, [%4];"
        : "=r"(r[0]), "=r"(r[1]), "=r"(r[2]), "=r"(r[3]) : "r"(addr));
}
__device__ __forceinline__ void ldsm4t(uint32_t* r, uint32_t addr) {
    asm volatile("ldmatrix.sync.aligned.m8n8.x4.trans.shared.b16 {%0,%1,%2,%3}, [%4];"
        : "=r"(r[0]), "=r"(r[1]), "=r"(r[2]), "=r"(r[3]) : "r"(addr));
}
__device__ __forceinline__ void mma16816(float* d, const uint32_t* a, const uint32_t* b) {
    asm volatile(
        "mma.sync.aligned.m16n8k16.row.col.f32.bf16.bf16.f32 "
        "{%0,%1,%2,%3}, {%4,%5,%6,%7}, {%8,%9}, {%0,%1,%2,%3};"
        : "+f"(d[0]), "+f"(d[1]), "+f"(d[2]), "+f"(d[3])
        : "r"(a[0]), "r"(a[1]), "r"(a[2]), "r"(a[3]), "r"(b[0]), "r"(b[1]));
}
__device__ __forceinline__ uint32_t packbf(float a, float b) {
    __nv_bfloat162 p;
    p.x = __float2bfloat16(a);
    p.y = __float2bfloat16(b);
    return *(uint32_t*)&p;
}

// ================= scratch (static device memory) ===========================
__device__ float g_att[4096 * 768];
__device__ float g_xn[4096];
__device__ float g_an[4096];
__device__ float g_wn1[2304];
__device__ float g_wn2[768];
__device__ __nv_bfloat16 g_qkvh[4096 * 2304], g_qkvl[4096 * 2304];
__device__ __nv_bfloat16 g_xhi[4096 * 768], g_xlo[4096 * 768];
__device__ __nv_bfloat16 g_ahi[4096 * 768], g_alo[4096 * 768];
__device__ __nv_bfloat16 g_w1hi[2304 * 768], g_w1lo[2304 * 768];
__device__ __nv_bfloat16 g_w2hi[768 * 768], g_w2lo[768 * 768];

// ================= prep kernels =============================================
__global__ void split_norm_k(const float* __restrict__ X, __nv_bfloat16* __restrict__ H,
                             __nv_bfloat16* __restrict__ L, float* __restrict__ nrm,
                             int M, int K) {
    int row = blockIdx.x * 8 + (threadIdx.x >> 5);
    int lane = threadIdx.x & 31;
    if (row >= M) return;
    const float* p = X + (long)row * K;
    float s = 0.f;
    for (int k = lane; k < K; k += 32) {
        float v = p[k];
        s = fmaf(v, v, s);
        __nv_bfloat16 hb = __float2bfloat16(v);
        H[(long)row * K + k] = hb;
        L[(long)row * K + k] = __float2bfloat16(v - __bfloat162float(hb));
    }
    #pragma unroll
    for (int o = 16; o; o >>= 1) s += __shfl_xor_sync(0xffffffffu, s, o);
    if (!lane) nrm[row] = s;
}

__global__ void rownorm_k(const float* __restrict__ X, float* __restrict__ o, int M, int K) {
    int row = blockIdx.x * 8 + (threadIdx.x >> 5);
    int lane = threadIdx.x & 31;
    if (row >= M) return;
    const float* p = X + (long)row * K;
    float s = 0.f;
    for (int k = lane; k < K; k += 32) { float v = p[k]; s = fmaf(v, v, s); }
    #pragma unroll
    for (int o2 = 16; o2; o2 >>= 1) s += __shfl_xor_sync(0xffffffffu, s, o2);
    if (!lane) o[row] = s;
}

__global__ void colnorm_k(const float* __restrict__ W, float* __restrict__ o, int K, int N) {
    int n = blockIdx.x * blockDim.x + threadIdx.x;
    if (n >= N) return;
    float s = 0.f;
    for (int k = 0; k < K; k++) { float v = W[(long)k * N + n]; s = fmaf(v, v, s); }
    o[n] = s;
}

__global__ void wtrans_split_k(const float* __restrict__ W, __nv_bfloat16* __restrict__ Th,
                               __nv_bfloat16* __restrict__ Tl, int K, int N) {
    __shared__ float t[32][33];
    int n0 = blockIdx.x * 32, k0 = blockIdx.y * 32;
    int tx = threadIdx.x, ty = threadIdx.y;  // (32, 8)
    #pragma unroll
    for (int j = 0; j < 32; j += 8)
        t[ty + j][tx] = W[(long)(k0 + ty + j) * N + n0 + tx];
    __syncthreads();
    #pragma unroll
    for (int j = 0; j < 32; j += 8) {
        float v = t[tx][ty + j];
        __nv_bfloat16 hb = __float2bfloat16(v);
        Th[(long)(n0 + ty + j) * K + k0 + tx] = hb;
        Tl[(long)(n0 + ty + j) * K + k0 + tx] = __float2bfloat16(v - __bfloat162float(hb));
    }
}

// ================= HMMA Yat-GEMM =============================================
#define BK 64
#define STR 144
#define MAT_BYTES (128 * STR)
#define BUF_BYTES (4 * MAT_BYTES)
#define GEMM_SMEM (2 * BUF_BYTES)

__global__ __launch_bounds__(256, 1)
void gemm_mma_k(const __nv_bfloat16* __restrict__ Ah, const __nv_bfloat16* __restrict__ Al,
                const __nv_bfloat16* __restrict__ Bh, const __nv_bfloat16* __restrict__ Bl,
                const float* __restrict__ bias, const float* __restrict__ rn,
                const float* __restrict__ cn, const float* __restrict__ alphaPtr,
                float* __restrict__ Cout,
                __nv_bfloat16* __restrict__ Ohi, __nv_bfloat16* __restrict__ Olo,
                int M, int N, int K, float baseF) {
    extern __shared__ char smc[];
    uint32_t sb = smem_u32(smc);
    int tid = threadIdx.x, wid = tid >> 5, lane = tid & 31;
    int M0 = blockIdx.y * 128, N0 = blockIdx.x * 128;
    int wm = wid & 1, wn = wid >> 1;

    float acc[4][4][4];
    #pragma unroll
    for (int i = 0; i < 4; i++)
        #pragma unroll
        for (int j = 0; j < 4; j++)
            #pragma unroll
            for (int u = 0; u < 4; u++) acc[i][j][u] = 0.f;

    const int NCH = K / BK;

    auto load_chunk = [&](int c, int buf) {
        int k0 = c * BK;
        uint32_t base = sb + buf * BUF_BYTES;
        #pragma unroll
        for (int l = 0; l < 4; l++) {
            int f = tid + l * 256;
            int row = f >> 3, seg = f & 7;
            uint32_t so = row * STR + seg * 16;
            long ga = (long)(M0 + row) * K + k0 + seg * 8;
            long gb = (long)(N0 + row) * K + k0 + seg * 8;
            cp16(base + so,                 Ah + ga);
            cp16(base + MAT_BYTES + so,     Al + ga);
            cp16(base + 2 * MAT_BYTES + so, Bh + gb);
            cp16(base + 3 * MAT_BYTES + so, Bl + gb);
        }
    };

    load_chunk(0, 0); CP_COMMIT();
    load_chunk(1, 1); CP_COMMIT();

    int gq = lane >> 3, rq = lane & 7;
    int arow = wm * 64 + (gq & 1) * 8 + rq;
    int acol8 = (gq >> 1) * 8;
    int brow = wn * 32 + (gq >> 1) * 8 + rq;
    int bcol8 = (gq & 1) * 8;

    for (int c = 0; c < NCH; c++) {
        if (c + 1 < NCH) { CP_WAIT1(); } else { CP_WAIT0(); }
        __syncthreads();
        uint32_t base = sb + (c & 1) * BUF_BYTES;
        uint32_t bAh = base, bAl = base + MAT_BYTES;
        uint32_t bBh = base + 2 * MAT_BYTES, bBl = base + 3 * MAT_BYTES;

        #pragma unroll
        for (int ks = 0; ks < BK / 16; ks++) {
            int kc = ks * 16;
            uint32_t ah[4][4], al[4][4], bh[4][2], bl[4][2];
            #pragma unroll
            for (int i = 0; i < 4; i++) {
                uint32_t off = (uint32_t)((arow + i * 16) * STR + (kc + acol8) * 2);
                ldsm4(ah[i], bAh + off);
                ldsm4(al[i], bAl + off);
            }
            #pragma unroll
            for (int jp = 0; jp < 2; jp++) {
                uint32_t off = (uint32_t)((brow + jp * 16) * STR + (kc + bcol8) * 2);
                uint32_t r[4];
                ldsm4(r, bBh + off);
                bh[jp * 2][0] = r[0]; bh[jp * 2][1] = r[1];
                bh[jp * 2 + 1][0] = r[2]; bh[jp * 2 + 1][1] = r[3];
                ldsm4(r, bBl + off);
                bl[jp * 2][0] = r[0]; bl[jp * 2][1] = r[1];
                bl[jp * 2 + 1][0] = r[2]; bl[jp * 2 + 1][1] = r[3];
            }
            #pragma unroll
            for (int i = 0; i < 4; i++)
                #pragma unroll
                for (int j = 0; j < 4; j++) {
                    mma16816(acc[i][j], ah[i], bh[j]);
                    mma16816(acc[i][j], ah[i], bl[j]);
                    mma16816(acc[i][j], al[i], bh[j]);
                }
        }
        if (c + 2 < NCH) {
            __syncthreads();
            load_chunk(c + 2, c & 1);
            CP_COMMIT();
        }
    }

    float alpha = __ldg(alphaPtr);
    float scaleF = powf(sqrtf(baseF) / logf(1.0f + baseF), alpha);
    int tq = lane >> 2, tr = lane & 3;
    #pragma unroll
    for (int i = 0; i < 4; i++) {
        int m0 = M0 + wm * 64 + i * 16 + tq;
        float rn0 = __ldg(&rn[m0]);
        float rn1 = __ldg(&rn[m0 + 8]);
        #pragma unroll
        for (int j = 0; j < 4; j++) {
            int n0 = N0 + wn * 32 + j * 8 + tr * 2;
            float cn0 = __ldg(&cn[n0]), cn1 = __ldg(&cn[n0 + 1]);
            float bb0 = __ldg(&bias[n0]), bb1 = __ldg(&bias[n0 + 1]);
            float c0 = acc[i][j][0], c1 = acc[i][j][1];
            float c2 = acc[i][j][2], c3 = acc[i][j][3];
            float2 r0, r1;
            r0.x = (c0 * c0 / (rn0 + cn0 - 2.f * c0 + EPSY) + bb0) * scaleF;
            r0.y = (c1 * c1 / (rn0 + cn1 - 2.f * c1 + EPSY) + bb1) * scaleF;
            r1.x = (c2 * c2 / (rn1 + cn0 - 2.f * c2 + EPSY) + bb0) * scaleF;
            r1.y = (c3 * c3 / (rn1 + cn1 - 2.f * c3 + EPSY) + bb1) * scaleF;
            if (Cout) {
                *(float2*)&Cout[(long)m0 * N + n0] = r0;
                *(float2*)&Cout[(long)(m0 + 8) * N + n0] = r1;
            }
            if (Ohi) {
                uint32_t h0 = packbf(r0.x, r0.y);
                uint32_t h1 = packbf(r1.x, r1.y);
                *(uint32_t*)&Ohi[(long)m0 * N + n0] = h0;
                *(uint32_t*)&Ohi[(long)(m0 + 8) * N + n0] = h1;
                __nv_bfloat162 hh0 = *(__nv_bfloat162*)&h0;
                __nv_bfloat162 hh1 = *(__nv_bfloat162*)&h1;
                uint32_t l0 = packbf(r0.x - __bfloat162float(hh0.x),
                                     r0.y - __bfloat162float(hh0.y));
                uint32_t l1 = packbf(r1.x - __bfloat162float(hh1.x),
                                     r1.y - __bfloat162float(hh1.y));
                *(uint32_t*)&Olo[(long)m0 * N + n0] = l0;
                *(uint32_t*)&Olo[(long)(m0 + 8) * N + n0] = l1;
            }
        }
    }
}

// ================= HMMA Yat flash attention ==================================
// CTA: 128 q rows for one (qt, h, b). 8 warps x 16 q rows.
// S = (QK^T)*0.125 via 3-product bf16 split; Yat transform; online softmax;
// O += P@V via 3-product split with P re-split in registers.
#define ASTR 144
#define AMAT (128 * ASTR)             // 18432
#define AQOFF 0                       // Qh, Ql (2 mats)
#define AKV0 (2 * AMAT)               // 36864
#define AKVSZ (4 * AMAT)              // 73728 per buffer (Kh,Kl,Vh,Vl)
#define AKN (AKV0 + 2 * AKVSZ)        // 184320
#define ATTN_SMEM (AKN + 2 * 512)     // 185344

__global__ __launch_bounds__(256, 1)
void attn_mma_k(const __nv_bfloat16* __restrict__ qh,
                const __nv_bfloat16* __restrict__ ql,
                float* __restrict__ outp,
                __nv_bfloat16* __restrict__ ohi, __nv_bfloat16* __restrict__ olo) {
    extern __shared__ char smc[];
    uint32_t sb = smem_u32(smc);
    int tid = threadIdx.x, wq = tid >> 5, lane = tid & 31;
    int qt = blockIdx.x, h = blockIdx.y, b = blockIdx.z;
    int q0 = qt * 128;
    const int T = 1024, C3 = 2304;
    long rbase = (long)b * T * C3;
    int qcol = h * 64, kcol = 768 + h * 64, vcol = 1536 + h * 64;

    auto loadQ = [&]() {
        #pragma unroll
        for (int l = 0; l < 4; l++) {
            int f = tid + l * 256;
            int row = f >> 3, seg = f & 7;
            long g = rbase + (long)(q0 + row) * C3 + qcol + seg * 8;
            uint32_t so = row * ASTR + seg * 16;
            cp16(sb + AQOFF + so, qh + g);
            cp16(sb + AQOFF + AMAT + so, ql + g);
        }
    };
    auto loadKV = [&](int kt, int buf) {
        int k0 = kt * 128;
        uint32_t base = sb + AKV0 + buf * AKVSZ;
        #pragma unroll
        for (int l = 0; l < 4; l++) {
            int f = tid + l * 256;
            int row = f >> 3, seg = f & 7;
            uint32_t so = row * ASTR + seg * 16;
            long gk = rbase + (long)(k0 + row) * C3 + kcol + seg * 8;
            long gv = rbase + (long)(k0 + row) * C3 + vcol + seg * 8;
            cp16(base + so,            qh + gk);
            cp16(base + AMAT + so,     ql + gk);
            cp16(base + 2 * AMAT + so, qh + gv);
            cp16(base + 3 * AMAT + so, ql + gv);
        }
    };

    loadQ(); loadKV(0, 0); CP_COMMIT();
    if (qt >= 1) { loadKV(1, 1); CP_COMMIT(); CP_WAIT1(); } else { CP_WAIT0(); }
    __syncthreads();

    // ---- Q fragments (registers for whole loop) + q norms ----
    int gq = lane >> 3, rq = lane & 7;
    int arow = wq * 16 + (gq & 1) * 8 + rq;
    int acol8 = (gq >> 1) * 8;
    uint32_t qfh[4][4], qfl[4][4];
    #pragma unroll
    for (int s = 0; s < 4; s++) {
        uint32_t off = (uint32_t)(arow * ASTR + (s * 16 + acol8) * 2);
        ldsm4(qfh[s], sb + AQOFF + off);
        ldsm4(qfl[s], sb + AQOFF + AMAT + off);
    }
    float qn0 = 0.f, qn1 = 0.f;
    #pragma unroll
    for (int s = 0; s < 4; s++)
        #pragma unroll
        for (int r = 0; r < 4; r++) {
            __nv_bfloat162 hh = *(__nv_bfloat162*)&qfh[s][r];
            __nv_bfloat162 ll = *(__nv_bfloat162*)&qfl[s][r];
            float v0 = __bfloat162float(hh.x) + __bfloat162float(ll.x);
            float v1 = __bfloat162float(hh.y) + __bfloat162float(ll.y);
            float ss = v0 * v0 + v1 * v1;
            if ((r & 1) == 0) qn0 += ss; else qn1 += ss;
        }
    qn0 += __shfl_xor_sync(0xffffffffu, qn0, 1);
    qn0 += __shfl_xor_sync(0xffffffffu, qn0, 2);
    qn1 += __shfl_xor_sync(0xffffffffu, qn1, 1);
    qn1 += __shfl_xor_sync(0xffffffffu, qn1, 2);

    int tq = lane >> 2, t = lane & 3;
    int gr0 = q0 + wq * 16 + tq, gr1 = gr0 + 8;
    float m0r = NEGINF, m1r = NEGINF, l0r = 0.f, l1r = 0.f;
    float O[8][4];
    #pragma unroll
    for (int j = 0; j < 8; j++)
        #pragma unroll
        for (int u = 0; u < 4; u++) O[j][u] = 0.f;

    for (int kt = 0; kt <= qt; kt++) {
        if (kt > 0) {
            if (kt + 1 <= qt) { CP_WAIT1(); } else { CP_WAIT0(); }
            __syncthreads();
        }
        uint32_t kvo = AKV0 + (kt & 1) * AKVSZ;
        uint32_t kno = AKN + (kt & 1) * 512;

        // ---- k norms from hi+lo ----
        {
            int row = tid >> 1, half = tid & 1;
            const __nv_bfloat162* ph =
                (const __nv_bfloat162*)(smc + kvo + row * ASTR + half * 64);
            const __nv_bfloat162* pl =
                (const __nv_bfloat162*)(smc + kvo + AMAT + row * ASTR + half * 64);
            float s = 0.f;
            #pragma unroll
            for (int d = 0; d < 16; d++) {
                __nv_bfloat162 hh = ph[d], ll = pl[d];
                float v0 = __bfloat162float(hh.x) + __bfloat162float(ll.x);
                float v1 = __bfloat162float(hh.y) + __bfloat162float(ll.y);
                s += v0 * v0 + v1 * v1;
            }
            s += __shfl_xor_sync(0xffffffffu, s, 1);
            if (!half) *(float*)(smc + kno + row * 4) = s;
        }
        __syncthreads();

        // ---- S = Q K^T (3-product split) ----
        float S[16][4];
        #pragma unroll
        for (int j = 0; j < 16; j++)
            #pragma unroll
            for (int u = 0; u < 4; u++) S[j][u] = 0.f;
        #pragma unroll
        for (int s = 0; s < 4; s++) {
            #pragma unroll
            for (int np = 0; np < 8; np++) {
                int browp = np * 16 + (gq >> 1) * 8 + rq;
                uint32_t off = (uint32_t)(browp * ASTR + (s * 16 + (gq & 1) * 8) * 2);
                uint32_t bh[4], bl[4];
                ldsm4(bh, sb + kvo + off);
                ldsm4(bl, sb + kvo + AMAT + off);
                mma16816(S[2 * np],     qfh[s], bh);
                mma16816(S[2 * np],     qfh[s], bl);
                mma16816(S[2 * np],     qfl[s], bh);
                mma16816(S[2 * np + 1], qfh[s], bh + 2);
                mma16816(S[2 * np + 1], qfh[s], bl + 2);
                mma16816(S[2 * np + 1], qfl[s], bh + 2);
            }
        }

        // ---- Yat transform + causal mask + online softmax ----
        bool diag = (kt == qt);
        int k0g = kt * 128;
        float mx0 = NEGINF, mx1 = NEGINF;
        #pragma unroll
        for (int j = 0; j < 16; j++) {
            int c0 = j * 8 + t * 2;
            float2 knv = *(float2*)(smc + kno + c0 * 4);
            int gc0 = k0g + c0, gc1 = gc0 + 1;
            float sc, den, lg;
            sc = S[j][0] * 0.125f; den = qn0 + knv.x - 2.f * sc + EPSY;
            lg = __fdividef(sc * sc, den);
            if (diag && gc0 > gr0) lg = NEGINF;
            S[j][0] = lg; mx0 = fmaxf(mx0, lg);
            sc = S[j][1] * 0.125f; den = qn0 + knv.y - 2.f * sc + EPSY;
            lg = __fdividef(sc * sc, den);
            if (diag && gc1 > gr0) lg = NEGINF;
            S[j][1] = lg; mx0 = fmaxf(mx0, lg);
            sc = S[j][2] * 0.125f; den = qn1 + knv.x - 2.f * sc + EPSY;
            lg = __fdividef(sc * sc, den);
            if (diag && gc0 > gr1) lg = NEGINF;
            S[j][2] = lg; mx1 = fmaxf(mx1, lg);
            sc = S[j][3] * 0.125f; den = qn1 + knv.y - 2.f * sc + EPSY;
            lg = __fdividef(sc * sc, den);
            if (diag && gc1 > gr1) lg = NEGINF;
            S[j][3] = lg; mx1 = fmaxf(mx1, lg);
        }
        mx0 = fmaxf(mx0, __shfl_xor_sync(0xffffffffu, mx0, 1));
        mx0 = fmaxf(mx0, __shfl_xor_sync(0xffffffffu, mx0, 2));
        mx1 = fmaxf(mx1, __shfl_xor_sync(0xffffffffu, mx1, 1));
        mx1 = fmaxf(mx1, __shfl_xor_sync(0xffffffffu, mx1, 2));
        float mn0 = fmaxf(m0r, mx0), mn1 = fmaxf(m1r, mx1);
        float cor0 = __expf(m0r - mn0), cor1 = __expf(m1r - mn1);
        float rs0 = 0.f, rs1 = 0.f;
        #pragma unroll
        for (int j = 0; j < 16; j++) {
            float p0 = __expf(S[j][0] - mn0); S[j][0] = p0; rs0 += p0;
            float p1 = __expf(S[j][1] - mn0); S[j][1] = p1; rs0 += p1;
            float p2 = __expf(S[j][2] - mn1); S[j][2] = p2; rs1 += p2;
            float p3 = __expf(S[j][3] - mn1); S[j][3] = p3; rs1 += p3;
        }
        rs0 += __shfl_xor_sync(0xffffffffu, rs0, 1);
        rs0 += __shfl_xor_sync(0xffffffffu, rs0, 2);
        rs1 += __shfl_xor_sync(0xffffffffu, rs1, 1);
        rs1 += __shfl_xor_sync(0xffffffffu, rs1, 2);
        l0r = l0r * cor0 + rs0; l1r = l1r * cor1 + rs1;
        m0r = mn0; m1r = mn1;
        #pragma unroll
        for (int j = 0; j < 8; j++) {
            O[j][0] *= cor0; O[j][1] *= cor0;
            O[j][2] *= cor1; O[j][3] *= cor1;
        }

        // ---- O += P @ V (P split in regs, V via ldmatrix.trans) ----
        int q4 = lane >> 3;
        #pragma unroll
        for (int s2 = 0; s2 < 8; s2++) {
            uint32_t ah[4], al[4];
            {
                float c0 = S[2 * s2][0], c1 = S[2 * s2][1];
                float c2 = S[2 * s2][2], c3 = S[2 * s2][3];
                float d0 = S[2 * s2 + 1][0], d1 = S[2 * s2 + 1][1];
                float d2 = S[2 * s2 + 1][2], d3 = S[2 * s2 + 1][3];
                ah[0] = packbf(c0, c1); ah[1] = packbf(c2, c3);
                ah[2] = packbf(d0, d1); ah[3] = packbf(d2, d3);
                __nv_bfloat162 h0 = *(__nv_bfloat162*)&ah[0];
                __nv_bfloat162 h1 = *(__nv_bfloat162*)&ah[1];
                __nv_bfloat162 h2 = *(__nv_bfloat162*)&ah[2];
                __nv_bfloat162 h3 = *(__nv_bfloat162*)&ah[3];
                al[0] = packbf(c0 - __bfloat162float(h0.x), c1 - __bfloat162float(h0.y));
                al[1] = packbf(c2 - __bfloat162float(h1.x), c3 - __bfloat162float(h1.y));
                al[2] = packbf(d0 - __bfloat162float(h2.x), d1 - __bfloat162float(h2.y));
                al[3] = packbf(d2 - __bfloat162float(h3.x), d3 - __bfloat162float(h3.y));
            }
            int vrow = s2 * 16 + (q4 & 1) * 8 + (lane & 7);
            #pragma unroll
            for (int g2 = 0; g2 < 4; g2++) {
                uint32_t off = (uint32_t)(vrow * ASTR + (g2 * 16 + (q4 >> 1) * 8) * 2);
                uint32_t bhv[4], blv[4];
                ldsm4t(bhv, sb + kvo + 2 * AMAT + off);
                ldsm4t(blv, sb + kvo + 3 * AMAT + off);
                mma16816(O[2 * g2],     ah, bhv);
                mma16816(O[2 * g2],     ah, blv);
                mma16816(O[2 * g2],     al, bhv);
                mma16816(O[2 * g2 + 1], ah, bhv + 2);
                mma16816(O[2 * g2 + 1], ah, blv + 2);
                mma16816(O[2 * g2 + 1], al, bhv + 2);
            }
        }

        if (kt + 2 <= qt) {
            __syncthreads();
            loadKV(kt + 2, kt & 1);
            CP_COMMIT();
        }
    }

    // ---- normalize + write fp32 + bf16 hi/lo split ----
    float inv0 = 1.f / l0r, inv1 = 1.f / l1r;
    long row0 = (long)b * T + q0 + wq * 16 + tq;
    #pragma unroll
    for (int j2 = 0; j2 < 8; j2++) {
        int col = h * 64 + j2 * 8 + t * 2;
        float v0 = O[j2][0] * inv0, v1 = O[j2][1] * inv0;
        float w0 = O[j2][2] * inv1, w1 = O[j2][3] * inv1;
        *(float2*)&outp[row0 * 768 + col] = make_float2(v0, v1);
        *(float2*)&outp[(row0 + 8) * 768 + col] = make_float2(w0, w1);
        uint32_t h0 = packbf(v0, v1), h1 = packbf(w0, w1);
        *(uint32_t*)&ohi[row0 * 768 + col] = h0;
        *(uint32_t*)&ohi[(row0 + 8) * 768 + col] = h1;
        __nv_bfloat162 hh0 = *(__nv_bfloat162*)&h0;
        __nv_bfloat162 hh1 = *(__nv_bfloat162*)&h1;
        *(uint32_t*)&olo[row0 * 768 + col] =
            packbf(v0 - __bfloat162float(hh0.x), v1 - __bfloat162float(hh0.y));
        *(uint32_t*)&olo[(row0 + 8) * 768 + col] =
            packbf(w0 - __bfloat162float(hh1.x), w1 - __bfloat162float(hh1.y));
    }
}

// ================= launch ====================================================
extern "C" void kernel_launch(void* const* d_in, const int* in_sizes, int n_in,
                              void* d_out, int out_size) {
    const float* x          = (const float*)d_in[0];
    // d_in[1] = causal tril mask — applied analytically
    const float* W_attn     = (const float*)d_in[2];
    const float* b_attn     = (const float*)d_in[3];
    const float* alpha_attn = (const float*)d_in[4];
    const float* W_proj     = (const float*)d_in[5];
    const float* b_proj     = (const float*)d_in[6];
    const float* alpha_proj = (const float*)d_in[7];
    float* out = (float*)d_out;

    float *p_att, *p_xn, *p_an, *p_wn1, *p_wn2;
    __nv_bfloat16 *p_qkvh, *p_qkvl, *p_xhi, *p_xlo, *p_ahi, *p_alo;
    __nv_bfloat16 *p_w1hi, *p_w1lo, *p_w2hi, *p_w2lo;
    cudaGetSymbolAddress((void**)&p_att, g_att);
    cudaGetSymbolAddress((void**)&p_xn, g_xn);
    cudaGetSymbolAddress((void**)&p_an, g_an);
    cudaGetSymbolAddress((void**)&p_wn1, g_wn1);
    cudaGetSymbolAddress((void**)&p_wn2, g_wn2);
    cudaGetSymbolAddress((void**)&p_qkvh, g_qkvh);
    cudaGetSymbolAddress((void**)&p_qkvl, g_qkvl);
    cudaGetSymbolAddress((void**)&p_xhi, g_xhi);
    cudaGetSymbolAddress((void**)&p_xlo, g_xlo);
    cudaGetSymbolAddress((void**)&p_ahi, g_ahi);
    cudaGetSymbolAddress((void**)&p_alo, g_alo);
    cudaGetSymbolAddress((void**)&p_w1hi, g_w1hi);
    cudaGetSymbolAddress((void**)&p_w1lo, g_w1lo);
    cudaGetSymbolAddress((void**)&p_w2hi, g_w2hi);
    cudaGetSymbolAddress((void**)&p_w2lo, g_w2lo);

    const int M = 4096, C = 768, F1 = 2304;

    cudaFuncSetAttribute(gemm_mma_k, cudaFuncAttributeMaxDynamicSharedMemorySize, GEMM_SMEM);
    cudaFuncSetAttribute(attn_mma_k, cudaFuncAttributeMaxDynamicSharedMemorySize, ATTN_SMEM);

    // ---- stage 1 prep
    split_norm_k<<<M / 8, 256>>>(x, p_xhi, p_xlo, p_xn, M, C);
    wtrans_split_k<<<dim3(F1 / 32, C / 32), dim3(32, 8)>>>(W_attn, p_w1hi, p_w1lo, C, F1);
    colnorm_k<<<F1 / 256, 256>>>(W_attn, p_wn1, C, F1);

    // ---- stage 1: HMMA Yat-GEMM -> qkv (bf16 hi/lo only)
    gemm_mma_k<<<dim3(F1 / 128, M / 128), 256, GEMM_SMEM>>>(
        p_xhi, p_xlo, p_w1hi, p_w1lo, b_attn, p_xn, p_wn1, alpha_attn,
        nullptr, p_qkvh, p_qkvl, M, F1, C, (float)F1);

    // ---- stage 2: HMMA Yat flash attention
    attn_mma_k<<<dim3(8, 12, 4), 256, ATTN_SMEM>>>(
        p_qkvh, p_qkvl, p_att, p_ahi, p_alo);

    // ---- stage 3 prep + HMMA Yat-GEMM -> out
    rownorm_k<<<M / 8, 256>>>(p_att, p_an, M, C);
    wtrans_split_k<<<dim3(C / 32, C / 32), dim3(32, 8)>>>(W_proj, p_w2hi, p_w2lo, C, C);
    colnorm_k<<<C / 256, 256>>>(W_proj, p_wn2, C, C);
    gemm_mma_k<<<dim3(C / 128, M / 128), 256, GEMM_SMEM>>>(
        p_ahi, p_alo, p_w2hi, p_w2lo, b_proj, p_an, p_wn2, alpha_proj,
        out, nullptr, nullptr, M, C, C, (float)C);
}

// round 9
// speedup vs baseline: 2.4997x; 1.0862x over previous
#include <cuda_runtime.h>
#include <cuda_bf16.h>
#include <cstdint>
#include <math.h>

#define EPSY (1.0f/137.0f)
#define NEGINF (-3.402823466e38f)

// ================= helpers ===================================================
__device__ __forceinline__ uint32_t smem_u32(const void* p) {
    uint32_t a;
    asm("{ .reg .u64 t; cvta.to.shared.u64 t, %1; cvt.u32.u64 %0, t; }"
        : "=r"(a) : "l"(p));
    return a;
}
__device__ __forceinline__ void cp16(uint32_t s, const void* g) {
    asm volatile("cp.async.cg.shared.global [%0], [%1], 16;" :: "r"(s), "l"(g));
}
#define CP_COMMIT() asm volatile("cp.async.commit_group;" ::: "memory")
#define CP_WAIT1()  asm volatile("cp.async.wait_group 1;" ::: "memory")
#define CP_WAIT0()  asm volatile("cp.async.wait_group 0;" ::: "memory")

__device__ __forceinline__ void ldsm4(uint32_t* r, uint32_t addr) {
    asm volatile("ldmatrix.sync.aligned.m8n8.x4.shared.b16 {%0,%1,%2,%3}, [%4];"
        : "=r"(r[0]), "=r"(r[1]), "=r"(r[2]), "=r"(r[3]) : "r"(addr));
}
__device__ __forceinline__ void ldsm4t(uint32_t* r, uint32_t addr) {
    asm volatile("ldmatrix.sync.aligned.m8n8.x4.trans.shared.b16 {%0,%1,%2,%3}, [%4];"
        : "=r"(r[0]), "=r"(r[1]), "=r"(r[2]), "=r"(r[3]) : "r"(addr));
}
__device__ __forceinline__ void mma16816(float* d, const uint32_t* a, const uint32_t* b) {
    asm volatile(
        "mma.sync.aligned.m16n8k16.row.col.f32.bf16.bf16.f32 "
        "{%0,%1,%2,%3}, {%4,%5,%6,%7}, {%8,%9}, {%0,%1,%2,%3};"
        : "+f"(d[0]), "+f"(d[1]), "+f"(d[2]), "+f"(d[3])
        : "r"(a[0]), "r"(a[1]), "r"(a[2]), "r"(a[3]), "r"(b[0]), "r"(b[1]));
}
__device__ __forceinline__ uint32_t packbf(float a, float b) {
    __nv_bfloat162 p;
    p.x = __float2bfloat16(a);
    p.y = __float2bfloat16(b);
    return *(uint32_t*)&p;
}

// ================= scratch (static device memory) ===========================
__device__ float g_xn[4096];
__device__ float g_an[4096];
__device__ float g_anp[4096 * 12];
__device__ float g_wn1[2304];
__device__ float g_wn2[768];
__device__ __nv_bfloat16 g_qkvh[4096 * 2304], g_qkvl[4096 * 2304];
__device__ __nv_bfloat16 g_xhi[4096 * 768], g_xlo[4096 * 768];
__device__ __nv_bfloat16 g_ahi[4096 * 768], g_alo[4096 * 768];
__device__ __nv_bfloat16 g_w1hi[2304 * 768], g_w1lo[2304 * 768];
__device__ __nv_bfloat16 g_w2hi[768 * 768], g_w2lo[768 * 768];

// ================= prep kernels =============================================
__global__ void split_norm_k(const float* __restrict__ X, __nv_bfloat16* __restrict__ H,
                             __nv_bfloat16* __restrict__ L, float* __restrict__ nrm,
                             int M, int K) {
    int row = blockIdx.x * 8 + (threadIdx.x >> 5);
    int lane = threadIdx.x & 31;
    if (row >= M) return;
    const float* p = X + (long)row * K;
    float s = 0.f;
    for (int k = lane; k < K; k += 32) {
        float v = p[k];
        s = fmaf(v, v, s);
        __nv_bfloat16 hb = __float2bfloat16(v);
        H[(long)row * K + k] = hb;
        L[(long)row * K + k] = __float2bfloat16(v - __bfloat162float(hb));
    }
    #pragma unroll
    for (int o = 16; o; o >>= 1) s += __shfl_xor_sync(0xffffffffu, s, o);
    if (!lane) nrm[row] = s;
}

__global__ void colnorm_k(const float* __restrict__ W, float* __restrict__ o, int K, int N) {
    int n = blockIdx.x * blockDim.x + threadIdx.x;
    if (n >= N) return;
    float s = 0.f;
    for (int k = 0; k < K; k++) { float v = W[(long)k * N + n]; s = fmaf(v, v, s); }
    o[n] = s;
}

__global__ void anred_k(const float* __restrict__ part, float* __restrict__ o) {
    int r = blockIdx.x * 256 + threadIdx.x;
    float s = 0.f;
    #pragma unroll
    for (int h = 0; h < 12; h++) s += part[r * 12 + h];
    o[r] = s;
}

__global__ void wtrans_split_k(const float* __restrict__ W, __nv_bfloat16* __restrict__ Th,
                               __nv_bfloat16* __restrict__ Tl, int K, int N) {
    __shared__ float t[32][33];
    int n0 = blockIdx.x * 32, k0 = blockIdx.y * 32;
    int tx = threadIdx.x, ty = threadIdx.y;  // (32, 8)
    #pragma unroll
    for (int j = 0; j < 32; j += 8)
        t[ty + j][tx] = W[(long)(k0 + ty + j) * N + n0 + tx];
    __syncthreads();
    #pragma unroll
    for (int j = 0; j < 32; j += 8) {
        float v = t[tx][ty + j];
        __nv_bfloat16 hb = __float2bfloat16(v);
        Th[(long)(n0 + ty + j) * K + k0 + tx] = hb;
        Tl[(long)(n0 + ty + j) * K + k0 + tx] = __float2bfloat16(v - __bfloat162float(hb));
    }
}

// ================= HMMA Yat-GEMM =============================================
#define BK 64
#define STR 144
#define MAT_BYTES (128 * STR)
#define BUF_BYTES (4 * MAT_BYTES)
#define GEMM_SMEM (2 * BUF_BYTES)

__global__ __launch_bounds__(256, 1)
void gemm_mma_k(const __nv_bfloat16* __restrict__ Ah, const __nv_bfloat16* __restrict__ Al,
                const __nv_bfloat16* __restrict__ Bh, const __nv_bfloat16* __restrict__ Bl,
                const float* __restrict__ bias, const float* __restrict__ rn,
                const float* __restrict__ cn, const float* __restrict__ alphaPtr,
                float* __restrict__ Cout,
                __nv_bfloat16* __restrict__ Ohi, __nv_bfloat16* __restrict__ Olo,
                int M, int N, int K, float baseF) {
    extern __shared__ char smc[];
    uint32_t sb = smem_u32(smc);
    int tid = threadIdx.x, wid = tid >> 5, lane = tid & 31;
    int M0 = blockIdx.y * 128, N0 = blockIdx.x * 128;
    int wm = wid & 1, wn = wid >> 1;

    float acc[4][4][4];
    #pragma unroll
    for (int i = 0; i < 4; i++)
        #pragma unroll
        for (int j = 0; j < 4; j++)
            #pragma unroll
            for (int u = 0; u < 4; u++) acc[i][j][u] = 0.f;

    const int NCH = K / BK;

    auto load_chunk = [&](int c, int buf) {
        int k0 = c * BK;
        uint32_t base = sb + buf * BUF_BYTES;
        #pragma unroll
        for (int l = 0; l < 4; l++) {
            int f = tid + l * 256;
            int row = f >> 3, seg = f & 7;
            uint32_t so = row * STR + seg * 16;
            long ga = (long)(M0 + row) * K + k0 + seg * 8;
            long gb = (long)(N0 + row) * K + k0 + seg * 8;
            cp16(base + so,                 Ah + ga);
            cp16(base + MAT_BYTES + so,     Al + ga);
            cp16(base + 2 * MAT_BYTES + so, Bh + gb);
            cp16(base + 3 * MAT_BYTES + so, Bl + gb);
        }
    };

    load_chunk(0, 0); CP_COMMIT();
    load_chunk(1, 1); CP_COMMIT();

    int gq = lane >> 3, rq = lane & 7;
    int arow = wm * 64 + (gq & 1) * 8 + rq;
    int acol8 = (gq >> 1) * 8;
    int brow = wn * 32 + (gq >> 1) * 8 + rq;
    int bcol8 = (gq & 1) * 8;

    // double-buffered register fragments (pipeline ldsm under mma)
    uint32_t ah[2][4][4], al[2][4][4], bh[2][4][2], bl[2][4][2];

    auto load_frags = [&](int ks, uint32_t base, int sl) {
        int kc = ks * 16;
        uint32_t bAh = base, bAl = base + MAT_BYTES;
        uint32_t bBh = base + 2 * MAT_BYTES, bBl = base + 3 * MAT_BYTES;
        #pragma unroll
        for (int i = 0; i < 4; i++) {
            uint32_t off = (uint32_t)((arow + i * 16) * STR + (kc + acol8) * 2);
            ldsm4(ah[sl][i], bAh + off);
            ldsm4(al[sl][i], bAl + off);
        }
        #pragma unroll
        for (int jp = 0; jp < 2; jp++) {
            uint32_t off = (uint32_t)((brow + jp * 16) * STR + (kc + bcol8) * 2);
            uint32_t r[4];
            ldsm4(r, bBh + off);
            bh[sl][jp * 2][0] = r[0]; bh[sl][jp * 2][1] = r[1];
            bh[sl][jp * 2 + 1][0] = r[2]; bh[sl][jp * 2 + 1][1] = r[3];
            ldsm4(r, bBl + off);
            bl[sl][jp * 2][0] = r[0]; bl[sl][jp * 2][1] = r[1];
            bl[sl][jp * 2 + 1][0] = r[2]; bl[sl][jp * 2 + 1][1] = r[3];
        }
    };

    for (int c = 0; c < NCH; c++) {
        if (c + 1 < NCH) { CP_WAIT1(); } else { CP_WAIT0(); }
        __syncthreads();
        uint32_t base = sb + (c & 1) * BUF_BYTES;
        load_frags(0, base, 0);

        #pragma unroll
        for (int ks = 0; ks < BK / 16; ks++) {
            int cur = ks & 1;
            if (ks + 1 < BK / 16) load_frags(ks + 1, base, cur ^ 1);
            #pragma unroll
            for (int i = 0; i < 4; i++)
                #pragma unroll
                for (int j = 0; j < 4; j++) {
                    mma16816(acc[i][j], ah[cur][i], bh[cur][j]);
                    mma16816(acc[i][j], ah[cur][i], bl[cur][j]);
                    mma16816(acc[i][j], al[cur][i], bh[cur][j]);
                }
        }
        if (c + 2 < NCH) {
            __syncthreads();
            load_chunk(c + 2, c & 1);
            CP_COMMIT();
        }
    }

    float alpha = __ldg(alphaPtr);
    float scaleF = powf(sqrtf(baseF) / logf(1.0f + baseF), alpha);
    int tq = lane >> 2, tr = lane & 3;
    #pragma unroll
    for (int i = 0; i < 4; i++) {
        int m0 = M0 + wm * 64 + i * 16 + tq;
        float rn0 = __ldg(&rn[m0]);
        float rn1 = __ldg(&rn[m0 + 8]);
        #pragma unroll
        for (int j = 0; j < 4; j++) {
            int n0 = N0 + wn * 32 + j * 8 + tr * 2;
            float cn0 = __ldg(&cn[n0]), cn1 = __ldg(&cn[n0 + 1]);
            float bb0 = __ldg(&bias[n0]), bb1 = __ldg(&bias[n0 + 1]);
            float c0 = acc[i][j][0], c1 = acc[i][j][1];
            float c2 = acc[i][j][2], c3 = acc[i][j][3];
            float2 r0, r1;
            r0.x = (c0 * c0 / (rn0 + cn0 - 2.f * c0 + EPSY) + bb0) * scaleF;
            r0.y = (c1 * c1 / (rn0 + cn1 - 2.f * c1 + EPSY) + bb1) * scaleF;
            r1.x = (c2 * c2 / (rn1 + cn0 - 2.f * c2 + EPSY) + bb0) * scaleF;
            r1.y = (c3 * c3 / (rn1 + cn1 - 2.f * c3 + EPSY) + bb1) * scaleF;
            if (Cout) {
                *(float2*)&Cout[(long)m0 * N + n0] = r0;
                *(float2*)&Cout[(long)(m0 + 8) * N + n0] = r1;
            }
            if (Ohi) {
                uint32_t h0 = packbf(r0.x, r0.y);
                uint32_t h1 = packbf(r1.x, r1.y);
                *(uint32_t*)&Ohi[(long)m0 * N + n0] = h0;
                *(uint32_t*)&Ohi[(long)(m0 + 8) * N + n0] = h1;
                __nv_bfloat162 hh0 = *(__nv_bfloat162*)&h0;
                __nv_bfloat162 hh1 = *(__nv_bfloat162*)&h1;
                uint32_t l0 = packbf(r0.x - __bfloat162float(hh0.x),
                                     r0.y - __bfloat162float(hh0.y));
                uint32_t l1 = packbf(r1.x - __bfloat162float(hh1.x),
                                     r1.y - __bfloat162float(hh1.y));
                *(uint32_t*)&Olo[(long)m0 * N + n0] = l0;
                *(uint32_t*)&Olo[(long)(m0 + 8) * N + n0] = l1;
            }
        }
    }
}

// ================= HMMA Yat flash attention ==================================
#define ASTR 144
#define AMAT (128 * ASTR)
#define AQOFF 0
#define AKV0 (2 * AMAT)
#define AKVSZ (4 * AMAT)
#define AKN (AKV0 + 2 * AKVSZ)
#define ATTN_SMEM (AKN + 2 * 512)

__global__ __launch_bounds__(256, 1)
void attn_mma_k(const __nv_bfloat16* __restrict__ qh,
                const __nv_bfloat16* __restrict__ ql,
                __nv_bfloat16* __restrict__ ohi, __nv_bfloat16* __restrict__ olo,
                float* __restrict__ anp) {
    extern __shared__ char smc[];
    uint32_t sb = smem_u32(smc);
    int tid = threadIdx.x, wq = tid >> 5, lane = tid & 31;
    int h = blockIdx.x, b = blockIdx.y;
    int qt = 7 - blockIdx.z;          // longest CTAs launch first
    int q0 = qt * 128;
    const int T = 1024, C3 = 2304;
    long rbase = (long)b * T * C3;
    int qcol = h * 64, kcol = 768 + h * 64, vcol = 1536 + h * 64;

    auto loadQ = [&]() {
        #pragma unroll
        for (int l = 0; l < 4; l++) {
            int f = tid + l * 256;
            int row = f >> 3, seg = f & 7;
            long g = rbase + (long)(q0 + row) * C3 + qcol + seg * 8;
            uint32_t so = row * ASTR + seg * 16;
            cp16(sb + AQOFF + so, qh + g);
            cp16(sb + AQOFF + AMAT + so, ql + g);
        }
    };
    auto loadKV = [&](int kt, int buf) {
        int k0 = kt * 128;
        uint32_t base = sb + AKV0 + buf * AKVSZ;
        #pragma unroll
        for (int l = 0; l < 4; l++) {
            int f = tid + l * 256;
            int row = f >> 3, seg = f & 7;
            uint32_t so = row * ASTR + seg * 16;
            long gk = rbase + (long)(k0 + row) * C3 + kcol + seg * 8;
            long gv = rbase + (long)(k0 + row) * C3 + vcol + seg * 8;
            cp16(base + so,            qh + gk);
            cp16(base + AMAT + so,     ql + gk);
            cp16(base + 2 * AMAT + so, qh + gv);
            cp16(base + 3 * AMAT + so, ql + gv);
        }
    };

    loadQ(); loadKV(0, 0); CP_COMMIT();
    if (qt >= 1) { loadKV(1, 1); CP_COMMIT(); CP_WAIT1(); } else { CP_WAIT0(); }
    __syncthreads();

    int gq = lane >> 3, rq = lane & 7;
    int arow = wq * 16 + (gq & 1) * 8 + rq;
    int acol8 = (gq >> 1) * 8;
    uint32_t qfh[4][4], qfl[4][4];
    #pragma unroll
    for (int s = 0; s < 4; s++) {
        uint32_t off = (uint32_t)(arow * ASTR + (s * 16 + acol8) * 2);
        ldsm4(qfh[s], sb + AQOFF + off);
        ldsm4(qfl[s], sb + AQOFF + AMAT + off);
    }
    float qn0 = 0.f, qn1 = 0.f;
    #pragma unroll
    for (int s = 0; s < 4; s++)
        #pragma unroll
        for (int r = 0; r < 4; r++) {
            __nv_bfloat162 hh = *(__nv_bfloat162*)&qfh[s][r];
            __nv_bfloat162 ll = *(__nv_bfloat162*)&qfl[s][r];
            float v0 = __bfloat162float(hh.x) + __bfloat162float(ll.x);
            float v1 = __bfloat162float(hh.y) + __bfloat162float(ll.y);
            float ss = v0 * v0 + v1 * v1;
            if ((r & 1) == 0) qn0 += ss; else qn1 += ss;
        }
    qn0 += __shfl_xor_sync(0xffffffffu, qn0, 1);
    qn0 += __shfl_xor_sync(0xffffffffu, qn0, 2);
    qn1 += __shfl_xor_sync(0xffffffffu, qn1, 1);
    qn1 += __shfl_xor_sync(0xffffffffu, qn1, 2);

    int tq = lane >> 2, t = lane & 3;
    int gr0 = q0 + wq * 16 + tq, gr1 = gr0 + 8;
    float m0r = NEGINF, m1r = NEGINF, l0r = 0.f, l1r = 0.f;
    float O[8][4];
    #pragma unroll
    for (int j = 0; j < 8; j++)
        #pragma unroll
        for (int u = 0; u < 4; u++) O[j][u] = 0.f;

    for (int kt = 0; kt <= qt; kt++) {
        if (kt > 0) {
            if (kt + 1 <= qt) { CP_WAIT1(); } else { CP_WAIT0(); }
            __syncthreads();
        }
        uint32_t kvo = AKV0 + (kt & 1) * AKVSZ;
        uint32_t kno = AKN + (kt & 1) * 512;

        {
            int row = tid >> 1, half = tid & 1;
            const __nv_bfloat162* ph =
                (const __nv_bfloat162*)(smc + kvo + row * ASTR + half * 64);
            const __nv_bfloat162* pl =
                (const __nv_bfloat162*)(smc + kvo + AMAT + row * ASTR + half * 64);
            float s = 0.f;
            #pragma unroll
            for (int d = 0; d < 16; d++) {
                __nv_bfloat162 hh = ph[d], ll = pl[d];
                float v0 = __bfloat162float(hh.x) + __bfloat162float(ll.x);
                float v1 = __bfloat162float(hh.y) + __bfloat162float(ll.y);
                s += v0 * v0 + v1 * v1;
            }
            s += __shfl_xor_sync(0xffffffffu, s, 1);
            if (!half) *(float*)(smc + kno + row * 4) = s;
        }
        __syncthreads();

        float S[16][4];
        #pragma unroll
        for (int j = 0; j < 16; j++)
            #pragma unroll
            for (int u = 0; u < 4; u++) S[j][u] = 0.f;
        #pragma unroll
        for (int s = 0; s < 4; s++) {
            #pragma unroll
            for (int np = 0; np < 8; np++) {
                int browp = np * 16 + (gq >> 1) * 8 + rq;
                uint32_t off = (uint32_t)(browp * ASTR + (s * 16 + (gq & 1) * 8) * 2);
                uint32_t bh[4], bl[4];
                ldsm4(bh, sb + kvo + off);
                ldsm4(bl, sb + kvo + AMAT + off);
                mma16816(S[2 * np],     qfh[s], bh);
                mma16816(S[2 * np],     qfh[s], bl);
                mma16816(S[2 * np],     qfl[s], bh);
                mma16816(S[2 * np + 1], qfh[s], bh + 2);
                mma16816(S[2 * np + 1], qfh[s], bl + 2);
                mma16816(S[2 * np + 1], qfl[s], bh + 2);
            }
        }

        bool diag = (kt == qt);
        int k0g = kt * 128;
        float mx0 = NEGINF, mx1 = NEGINF;
        #pragma unroll
        for (int j = 0; j < 16; j++) {
            int c0 = j * 8 + t * 2;
            float2 knv = *(float2*)(smc + kno + c0 * 4);
            int gc0 = k0g + c0, gc1 = gc0 + 1;
            float sc, den, lg;
            sc = S[j][0] * 0.125f; den = qn0 + knv.x - 2.f * sc + EPSY;
            lg = __fdividef(sc * sc, den);
            if (diag && gc0 > gr0) lg = NEGINF;
            S[j][0] = lg; mx0 = fmaxf(mx0, lg);
            sc = S[j][1] * 0.125f; den = qn0 + knv.y - 2.f * sc + EPSY;
            lg = __fdividef(sc * sc, den);
            if (diag && gc1 > gr0) lg = NEGINF;
            S[j][1] = lg; mx0 = fmaxf(mx0, lg);
            sc = S[j][2] * 0.125f; den = qn1 + knv.x - 2.f * sc + EPSY;
            lg = __fdividef(sc * sc, den);
            if (diag && gc0 > gr1) lg = NEGINF;
            S[j][2] = lg; mx1 = fmaxf(mx1, lg);
            sc = S[j][3] * 0.125f; den = qn1 + knv.y - 2.f * sc + EPSY;
            lg = __fdividef(sc * sc, den);
            if (diag && gc1 > gr1) lg = NEGINF;
            S[j][3] = lg; mx1 = fmaxf(mx1, lg);
        }
        mx0 = fmaxf(mx0, __shfl_xor_sync(0xffffffffu, mx0, 1));
        mx0 = fmaxf(mx0, __shfl_xor_sync(0xffffffffu, mx0, 2));
        mx1 = fmaxf(mx1, __shfl_xor_sync(0xffffffffu, mx1, 1));
        mx1 = fmaxf(mx1, __shfl_xor_sync(0xffffffffu, mx1, 2));
        float mn0 = fmaxf(m0r, mx0), mn1 = fmaxf(m1r, mx1);
        float cor0 = __expf(m0r - mn0), cor1 = __expf(m1r - mn1);
        float rs0 = 0.f, rs1 = 0.f;
        #pragma unroll
        for (int j = 0; j < 16; j++) {
            float p0 = __expf(S[j][0] - mn0); S[j][0] = p0; rs0 += p0;
            float p1 = __expf(S[j][1] - mn0); S[j][1] = p1; rs0 += p1;
            float p2 = __expf(S[j][2] - mn1); S[j][2] = p2; rs1 += p2;
            float p3 = __expf(S[j][3] - mn1); S[j][3] = p3; rs1 += p3;
        }
        rs0 += __shfl_xor_sync(0xffffffffu, rs0, 1);
        rs0 += __shfl_xor_sync(0xffffffffu, rs0, 2);
        rs1 += __shfl_xor_sync(0xffffffffu, rs1, 1);
        rs1 += __shfl_xor_sync(0xffffffffu, rs1, 2);
        l0r = l0r * cor0 + rs0; l1r = l1r * cor1 + rs1;
        m0r = mn0; m1r = mn1;
        #pragma unroll
        for (int j = 0; j < 8; j++) {
            O[j][0] *= cor0; O[j][1] *= cor0;
            O[j][2] *= cor1; O[j][3] *= cor1;
        }

        int q4 = lane >> 3;
        #pragma unroll
        for (int s2 = 0; s2 < 8; s2++) {
            uint32_t ah[4], al[4];
            {
                float c0 = S[2 * s2][0], c1 = S[2 * s2][1];
                float c2 = S[2 * s2][2], c3 = S[2 * s2][3];
                float d0 = S[2 * s2 + 1][0], d1 = S[2 * s2 + 1][1];
                float d2 = S[2 * s2 + 1][2], d3 = S[2 * s2 + 1][3];
                ah[0] = packbf(c0, c1); ah[1] = packbf(c2, c3);
                ah[2] = packbf(d0, d1); ah[3] = packbf(d2, d3);
                __nv_bfloat162 h0 = *(__nv_bfloat162*)&ah[0];
                __nv_bfloat162 h1 = *(__nv_bfloat162*)&ah[1];
                __nv_bfloat162 h2 = *(__nv_bfloat162*)&ah[2];
                __nv_bfloat162 h3 = *(__nv_bfloat162*)&ah[3];
                al[0] = packbf(c0 - __bfloat162float(h0.x), c1 - __bfloat162float(h0.y));
                al[1] = packbf(c2 - __bfloat162float(h1.x), c3 - __bfloat162float(h1.y));
                al[2] = packbf(d0 - __bfloat162float(h2.x), d1 - __bfloat162float(h2.y));
                al[3] = packbf(d2 - __bfloat162float(h3.x), d3 - __bfloat162float(h3.y));
            }
            int vrow = s2 * 16 + (q4 & 1) * 8 + (lane & 7);
            #pragma unroll
            for (int g2 = 0; g2 < 4; g2++) {
                uint32_t off = (uint32_t)(vrow * ASTR + (g2 * 16 + (q4 >> 1) * 8) * 2);
                uint32_t bhv[4], blv[4];
                ldsm4t(bhv, sb + kvo + 2 * AMAT + off);
                ldsm4t(blv, sb + kvo + 3 * AMAT + off);
                mma16816(O[2 * g2],     ah, bhv);
                mma16816(O[2 * g2],     ah, blv);
                mma16816(O[2 * g2],     al, bhv);
                mma16816(O[2 * g2 + 1], ah, bhv + 2);
                mma16816(O[2 * g2 + 1], ah, blv + 2);
                mma16816(O[2 * g2 + 1], al, bhv + 2);
            }
        }

        if (kt + 2 <= qt) {
            __syncthreads();
            loadKV(kt + 2, kt & 1);
            CP_COMMIT();
        }
    }

    // ---- normalize + write bf16 hi/lo + per-head partial row norms ----
    float inv0 = 1.f / l0r, inv1 = 1.f / l1r;
    long row0 = (long)b * T + q0 + wq * 16 + tq;
    float ns0 = 0.f, ns1 = 0.f;
    #pragma unroll
    for (int j2 = 0; j2 < 8; j2++) {
        int col = h * 64 + j2 * 8 + t * 2;
        float v0 = O[j2][0] * inv0, v1 = O[j2][1] * inv0;
        float w0 = O[j2][2] * inv1, w1 = O[j2][3] * inv1;
        ns0 += v0 * v0 + v1 * v1;
        ns1 += w0 * w0 + w1 * w1;
        uint32_t h0 = packbf(v0, v1), h1 = packbf(w0, w1);
        *(uint32_t*)&ohi[row0 * 768 + col] = h0;
        *(uint32_t*)&ohi[(row0 + 8) * 768 + col] = h1;
        __nv_bfloat162 hh0 = *(__nv_bfloat162*)&h0;
        __nv_bfloat162 hh1 = *(__nv_bfloat162*)&h1;
        *(uint32_t*)&olo[row0 * 768 + col] =
            packbf(v0 - __bfloat162float(hh0.x), v1 - __bfloat162float(hh0.y));
        *(uint32_t*)&olo[(row0 + 8) * 768 + col] =
            packbf(w0 - __bfloat162float(hh1.x), w1 - __bfloat162float(hh1.y));
    }
    ns0 += __shfl_xor_sync(0xffffffffu, ns0, 1);
    ns0 += __shfl_xor_sync(0xffffffffu, ns0, 2);
    ns1 += __shfl_xor_sync(0xffffffffu, ns1, 1);
    ns1 += __shfl_xor_sync(0xffffffffu, ns1, 2);
    if (t == 0) {
        anp[row0 * 12 + h] = ns0;
        anp[(row0 + 8) * 12 + h] = ns1;
    }
}

// ================= launch ====================================================
extern "C" void kernel_launch(void* const* d_in, const int* in_sizes, int n_in,
                              void* d_out, int out_size) {
    const float* x          = (const float*)d_in[0];
    // d_in[1] = causal tril mask — applied analytically
    const float* W_attn     = (const float*)d_in[2];
    const float* b_attn     = (const float*)d_in[3];
    const float* alpha_attn = (const float*)d_in[4];
    const float* W_proj     = (const float*)d_in[5];
    const float* b_proj     = (const float*)d_in[6];
    const float* alpha_proj = (const float*)d_in[7];
    float* out = (float*)d_out;

    float *p_xn, *p_an, *p_anp, *p_wn1, *p_wn2;
    __nv_bfloat16 *p_qkvh, *p_qkvl, *p_xhi, *p_xlo, *p_ahi, *p_alo;
    __nv_bfloat16 *p_w1hi, *p_w1lo, *p_w2hi, *p_w2lo;
    cudaGetSymbolAddress((void**)&p_xn, g_xn);
    cudaGetSymbolAddress((void**)&p_an, g_an);
    cudaGetSymbolAddress((void**)&p_anp, g_anp);
    cudaGetSymbolAddress((void**)&p_wn1, g_wn1);
    cudaGetSymbolAddress((void**)&p_wn2, g_wn2);
    cudaGetSymbolAddress((void**)&p_qkvh, g_qkvh);
    cudaGetSymbolAddress((void**)&p_qkvl, g_qkvl);
    cudaGetSymbolAddress((void**)&p_xhi, g_xhi);
    cudaGetSymbolAddress((void**)&p_xlo, g_xlo);
    cudaGetSymbolAddress((void**)&p_ahi, g_ahi);
    cudaGetSymbolAddress((void**)&p_alo, g_alo);
    cudaGetSymbolAddress((void**)&p_w1hi, g_w1hi);
    cudaGetSymbolAddress((void**)&p_w1lo, g_w1lo);
    cudaGetSymbolAddress((void**)&p_w2hi, g_w2hi);
    cudaGetSymbolAddress((void**)&p_w2lo, g_w2lo);

    const int M = 4096, C = 768, F1 = 2304;

    cudaFuncSetAttribute(gemm_mma_k, cudaFuncAttributeMaxDynamicSharedMemorySize, GEMM_SMEM);
    cudaFuncSetAttribute(attn_mma_k, cudaFuncAttributeMaxDynamicSharedMemorySize, ATTN_SMEM);

    // ---- stage 1 prep
    split_norm_k<<<M / 8, 256>>>(x, p_xhi, p_xlo, p_xn, M, C);
    wtrans_split_k<<<dim3(F1 / 32, C / 32), dim3(32, 8)>>>(W_attn, p_w1hi, p_w1lo, C, F1);
    colnorm_k<<<F1 / 256, 256>>>(W_attn, p_wn1, C, F1);

    // ---- stage 1: HMMA Yat-GEMM -> qkv (bf16 hi/lo)
    gemm_mma_k<<<dim3(F1 / 128, M / 128), 256, GEMM_SMEM>>>(
        p_xhi, p_xlo, p_w1hi, p_w1lo, b_attn, p_xn, p_wn1, alpha_attn,
        nullptr, p_qkvh, p_qkvl, M, F1, C, (float)F1);

    // ---- stage 2: HMMA Yat flash attention (longest-first CTA order,
    //      fused bf16 split + per-head row-norm partials)
    attn_mma_k<<<dim3(12, 4, 8), 256, ATTN_SMEM>>>(
        p_qkvh, p_qkvl, p_ahi, p_alo, p_anp);

    // ---- stage 3 prep + HMMA Yat-GEMM -> out
    anred_k<<<M / 256, 256>>>(p_anp, p_an);
    wtrans_split_k<<<dim3(C / 32, C / 32), dim3(32, 8)>>>(W_proj, p_w2hi, p_w2lo, C, C);
    colnorm_k<<<C / 256, 256>>>(W_proj, p_wn2, C, C);
    gemm_mma_k<<<dim3(C / 128, M / 128), 256, GEMM_SMEM>>>(
        p_ahi, p_alo, p_w2hi, p_w2lo, b_proj, p_an, p_wn2, alpha_proj,
        out, nullptr, nullptr, M, C, C, (float)C);
}